// round 7
// baseline (speedup 1.0000x reference)
#include <cuda_runtime.h>
#include <cuda_fp16.h>
#include <cstdint>

#define NB    8
#define DIM   512
#define LSEQ  2304
#define FD    512
#define MTOT  (NB * LSEQ)         // 18432
#define MF    ((size_t)MTOT * FD) // 9437184
#define EPSN  1e-5f
#define SCORE_SCALE 0.044194173824159216f   // 1/sqrt(512)

typedef __half fp16;

// ---------------- scratch (device globals) ----------------
__device__ fp16  g_flat_h[MF], g_flat_l[MF];         // x^T hi/lo (A of proj)
__device__ fp16  g_Wh[3][FD * DIM];                  // W rounded once (B side)
__device__ fp16  g_Qh[MF], g_Ql[MF];                 // A of scores: hi+lo
__device__ fp16  g_Kh[MF];
__device__ fp16  g_Vh[MF];
__device__ fp16  g_VTh[MF];                          // V^T per batch (F, L)
__device__ fp16  g_Ph[(size_t)NB * LSEQ * LSEQ], g_Pl[(size_t)NB * LSEQ * LSEQ];
__device__ float g_S[(size_t)NB * LSEQ * LSEQ];      // scores fp32; front 3*MF floats = raw QKV

// ---------------- PTX helpers (plain sm_80+ target only) ----------------
__device__ __forceinline__ uint32_t smem_u32(const void* p) {
    uint32_t a;
    asm("{ .reg .u64 t; cvta.to.shared.u64 t, %1; cvt.u32.u64 %0, t; }" : "=r"(a) : "l"(p));
    return a;
}
__device__ __forceinline__ void cp16(uint32_t dst, const void* src) {
    asm volatile("cp.async.cg.shared.global [%0], [%1], 16;" :: "r"(dst), "l"(src));
}
#define CP_COMMIT() asm volatile("cp.async.commit_group;" ::: "memory")
#define CP_WAIT(N)  asm volatile("cp.async.wait_group %0;" :: "n"(N) : "memory")

__device__ __forceinline__ void ldsm4(uint32_t* r, uint32_t addr) {
    asm volatile("ldmatrix.sync.aligned.m8n8.x4.shared.b16 {%0,%1,%2,%3}, [%4];"
                 : "=r"(r[0]), "=r"(r[1]), "=r"(r[2]), "=r"(r[3]) : "r"(addr));
}
// fp32-accumulate (hi term)
__device__ __forceinline__ void mma_f32(float* c, const uint32_t* a, const uint32_t* b) {
    asm volatile("mma.sync.aligned.m16n8k16.row.col.f32.f16.f16.f32 "
                 "{%0,%1,%2,%3}, {%4,%5,%6,%7}, {%8,%9}, {%0,%1,%2,%3};"
                 : "+f"(c[0]), "+f"(c[1]), "+f"(c[2]), "+f"(c[3])
                 : "r"(a[0]), "r"(a[1]), "r"(a[2]), "r"(a[3]), "r"(b[0]), "r"(b[1]));
}
// fp16-accumulate (lo term; partial sums are O(1e-1) max -> fp16 safe)
__device__ __forceinline__ void mma_f16(uint32_t* c, const uint32_t* a, const uint32_t* b) {
    asm volatile("mma.sync.aligned.m16n8k16.row.col.f16.f16.f16.f16 "
                 "{%0,%1}, {%2,%3,%4,%5}, {%6,%7}, {%0,%1};"
                 : "+r"(c[0]), "+r"(c[1])
                 : "r"(a[0]), "r"(a[1]), "r"(a[2]), "r"(a[3]), "r"(b[0]), "r"(b[1]));
}

__device__ __forceinline__ void split2(float v, fp16& h, fp16& l) {
    h = __float2half_rn(v);
    l = __float2half_rn(v - __half2float(h));
}

// ---------------- SMEM geometry ----------------
// tile: 128 rows x 64 fp16 = 128B/row, XOR-swizzled (no pad) = 16384 B
#define TB      16384
#define STAGEB  (3 * TB)          // Ah | Al | Bh
#define GEMM_SMEM (2 * STAGEB)    // 98304 B (2 CTAs/SM)

// ===========================================================================
// 2-term split-fp16 GEMM: C[m,n] = sum_k (Ah+Al)[m,k] * Bh[n,k]
// hi term -> fp32 accum, lo term -> fp16 accum (rate probe).
// A,B K-major with ld == K. EPI: 0 = tanh(acc+bias), 1 = acc*scale, 2 = none
// ===========================================================================
template <int EPI>
__global__ void __launch_bounds__(256, 2) gemm2(
    const fp16* __restrict__ Ah, const fp16* __restrict__ Al,
    const fp16* __restrict__ Bh,
    float* __restrict__ C, const float* __restrict__ bias,
    int K, int ldc,
    long long sA, long long sB, long long sC, float scale)
{
    extern __shared__ char smem[];
    const uint32_t sbase = smem_u32(smem);
    const int tid  = threadIdx.x;
    const int lane = tid & 31, wid = tid >> 5;
    const int wm = wid >> 2, wn = wid & 3;

    const int m0 = blockIdx.y * 128;
    const int f0 = blockIdx.x * 128;
    Ah += (long long)blockIdx.z * sA + (size_t)m0 * K;
    Al += (long long)blockIdx.z * sA + (size_t)m0 * K;
    Bh += (long long)blockIdx.z * sB + (size_t)f0 * K;
    C  += (long long)blockIdx.z * sC;

    // cp.async mapping: thread t -> row r = t>>1, chunks (t&1)*4 + q
    const int ldrow  = tid >> 1;
    const int ldcb   = (tid & 1) * 4;
    const int ldxor  = ldrow & 7;
    const size_t gA0 = (size_t)ldrow * K + ldcb * 8;
    const uint32_t ldRow128 = (uint32_t)(ldrow * 128);

    // ldmatrix mapping
    const int j = lane & 7, g = lane >> 3;
    const int aColSel = g >> 1, bColSel = g & 1;
    const uint32_t aRowB = (uint32_t)((wm * 64 + (g & 1) * 8 + j) * 128);
    const uint32_t bRowB = (uint32_t)((wn * 32 + (g >> 1) * 8 + j) * 128);

    float    acc [4][4][4];
    uint32_t accl[4][4][2];
#pragma unroll
    for (int a = 0; a < 4; a++)
#pragma unroll
        for (int b = 0; b < 4; b++) {
#pragma unroll
            for (int r = 0; r < 4; r++) acc[a][b][r] = 0.0f;
            accl[a][b][0] = 0u; accl[a][b][1] = 0u;
        }

    const int NIT = K >> 6;   // K / 64

    auto load_stage = [&](int st, int k0) {
        const uint32_t base = sbase + st * STAGEB + ldRow128;
#pragma unroll
        for (int q = 0; q < 4; ++q) {
            const int c16 = ldcb + q;
            const uint32_t d = base + (uint32_t)((c16 ^ ldxor) * 16);
            cp16(d,          Ah + gA0 + k0 + q * 8);
            cp16(d + TB,     Al + gA0 + k0 + q * 8);
            cp16(d + 2 * TB, Bh + gA0 + k0 + q * 8);   // gB0 == gA0 since ld == K
        }
    };

    load_stage(0, 0);
    CP_COMMIT();
    if (NIT > 1) load_stage(1, 64);
    CP_COMMIT();

    for (int it = 0; it < NIT; ++it) {
        CP_WAIT(1);
        __syncthreads();
        const uint32_t sb = sbase + (it & 1) * STAGEB;
#pragma unroll
        for (int c = 0; c < 4; ++c) {          // four k16 blocks per stage
            const uint32_t bPhys = (uint32_t)((((2 * c) + bColSel) ^ j) * 16);
            const uint32_t aPhys = (uint32_t)((((2 * c) + aColSel) ^ j) * 16);
            uint32_t bh[8];
            ldsm4(bh,     sb + 2 * TB + bRowB + bPhys);
            ldsm4(bh + 4, sb + 2 * TB + bRowB + 16 * 128 + bPhys);
#pragma unroll
            for (int mi = 0; mi < 4; ++mi) {
                uint32_t ah[4], al[4];
                ldsm4(ah, sb +      aRowB + mi * (16 * 128) + aPhys);
                ldsm4(al, sb + TB + aRowB + mi * (16 * 128) + aPhys);
#pragma unroll
                for (int ni = 0; ni < 4; ++ni) mma_f32(acc[mi][ni],  ah, &bh[ni * 2]);
#pragma unroll
                for (int ni = 0; ni < 4; ++ni) mma_f16(accl[mi][ni], al, &bh[ni * 2]);
            }
        }
        __syncthreads();
        if (it + 2 < NIT) load_stage(it & 1, (it + 2) * 64);
        CP_COMMIT();
    }

    // epilogue: combine hi (fp32) + lo (fp16) accumulators
    const int qp = lane & 3, rr = lane >> 2;
#pragma unroll
    for (int mi = 0; mi < 4; ++mi) {
#pragma unroll
        for (int ni = 0; ni < 4; ++ni) {
            const int row = m0 + wm * 64 + mi * 16 + rr;
            const int col = f0 + wn * 32 + ni * 8 + qp * 2;
            const __half2 l0 = *(const __half2*)&accl[mi][ni][0];
            const __half2 l1 = *(const __half2*)&accl[mi][ni][1];
            float2 v0 = make_float2(acc[mi][ni][0] + __low2float(l0),
                                    acc[mi][ni][1] + __high2float(l0));
            float2 v1 = make_float2(acc[mi][ni][2] + __low2float(l1),
                                    acc[mi][ni][3] + __high2float(l1));
            if (EPI == 0) {
                float2 b = *(const float2*)(bias + col);
                v0.x = tanhf(v0.x + b.x); v0.y = tanhf(v0.y + b.y);
                v1.x = tanhf(v1.x + b.x); v1.y = tanhf(v1.y + b.y);
            } else if (EPI == 1) {
                v0.x *= scale; v0.y *= scale; v1.x *= scale; v1.y *= scale;
            }
            *(float2*)(C + (size_t)row * ldc + col)       = v0;
            *(float2*)(C + (size_t)(row + 8) * ldc + col) = v1;
        }
    }
}

// ===========================================================================
// x (N,D,L) -> flat hi/lo (M,D) fp16 (transpose + split)
// ===========================================================================
__global__ __launch_bounds__(256) void xsplit(const float* __restrict__ x,
                                              fp16* __restrict__ oh, fp16* __restrict__ ol)
{
    __shared__ float t[32][33];
    const int z = blockIdx.z;
    const float* in = x + (size_t)z * DIM * LSEQ;
    const int l0 = blockIdx.x * 32, d0 = blockIdx.y * 32;
    const int xx = threadIdx.x & 31, yy = threadIdx.x >> 5;
#pragma unroll
    for (int i = 0; i < 32; i += 8)
        t[yy + i][xx] = in[(size_t)(d0 + yy + i) * LSEQ + l0 + xx];
    __syncthreads();
#pragma unroll
    for (int i = 0; i < 32; i += 8) {
        float v = t[xx][yy + i];
        size_t o = (size_t)(z * LSEQ + l0 + yy + i) * DIM + d0 + xx;
        fp16 h, l; split2(v, h, l);
        oh[o] = h; ol[o] = l;
    }
}

// weights: round once to fp16; grid.y selects q/k/v
__global__ __launch_bounds__(256) void wsplit(const float* __restrict__ wq,
                                              const float* __restrict__ wk,
                                              const float* __restrict__ wv,
                                              fp16* __restrict__ h)
{
    const int n = FD * DIM;
    const float* w = (blockIdx.y == 0) ? wq : (blockIdx.y == 1) ? wk : wv;
    int i = blockIdx.x * 256 + threadIdx.x;
    if (i < n) h[blockIdx.y * n + i] = __float2half_rn(w[i]);
}

// ===========================================================================
// double instance norm: raw fp32 row -> fp16 (grid.y: 0=Q hi+lo, 1=K hi, 2=V hi)
// ===========================================================================
__device__ __forceinline__ float rsum128(float x, volatile float* red, int tid)
{
#pragma unroll
    for (int o = 16; o > 0; o >>= 1) x += __shfl_down_sync(0xffffffffu, x, o);
    if ((tid & 31) == 0) red[tid >> 5] = x;
    __syncthreads();
    float t = (red[0] + red[1]) + (red[2] + red[3]);
    __syncthreads();
    return t;
}

__global__ __launch_bounds__(128) void inorm_split(const float* __restrict__ raw,
                                                   fp16* __restrict__ qh, fp16* __restrict__ ql,
                                                   fp16* __restrict__ kh, fp16* __restrict__ vh)
{
    const int which = blockIdx.y;
    raw += (size_t)which * MF;
    fp16* oh = (which == 0) ? qh : (which == 1) ? kh : vh;
    fp16* ol = (which == 0) ? ql : nullptr;

    const float4* row = (const float4*)(raw + (size_t)blockIdx.x * FD);
    __shared__ float red[4];
    const int tid = threadIdx.x;
    float4 v = row[tid];

    float s  = rsum128(v.x + v.y + v.z + v.w, red, tid);
    float mu = s * (1.0f / FD);
    v.x -= mu; v.y -= mu; v.z -= mu; v.w -= mu;
    float sq = rsum128(v.x * v.x + v.y * v.y + v.z * v.z + v.w * v.w, red, tid);
    float r1 = rsqrtf(sq * (1.0f / FD) + EPSN);
    v.x *= r1; v.y *= r1; v.z *= r1; v.w *= r1;

    float s2  = rsum128(v.x + v.y + v.z + v.w, red, tid);
    float mu2 = s2 * (1.0f / FD);
    v.x -= mu2; v.y -= mu2; v.z -= mu2; v.w -= mu2;
    float sq2 = rsum128(v.x * v.x + v.y * v.y + v.z * v.z + v.w * v.w, red, tid);
    float r2  = rsqrtf(sq2 * (1.0f / FD) + EPSN);
    v.x *= r2; v.y *= r2; v.z *= r2; v.w *= r2;

    size_t o = (size_t)blockIdx.x * FD + tid * 4;
    fp16 h, l;
    split2(v.x, h, l); oh[o]     = h; if (ol) ol[o]     = l;
    split2(v.y, h, l); oh[o + 1] = h; if (ol) ol[o + 1] = l;
    split2(v.z, h, l); oh[o + 2] = h; if (ol) ol[o + 2] = l;
    split2(v.w, h, l); oh[o + 3] = h; if (ol) ol[o + 3] = l;
}

// ===========================================================================
// softmax: fp32 scores row -> fp16 hi/lo prob row
// ===========================================================================
__global__ __launch_bounds__(256) void softmax_split(const float* __restrict__ S,
                                                     fp16* __restrict__ ph, fp16* __restrict__ pl)
{
    const float* row = S + (size_t)blockIdx.x * LSEQ;
    __shared__ float red[8];
    const int tid = threadIdx.x;

    float v[9];
    float mx = -1e30f;
#pragma unroll
    for (int i = 0; i < 9; i++) { v[i] = row[tid + i * 256]; mx = fmaxf(mx, v[i]); }
#pragma unroll
    for (int o = 16; o > 0; o >>= 1) mx = fmaxf(mx, __shfl_xor_sync(0xffffffffu, mx, o));
    if ((tid & 31) == 0) red[tid >> 5] = mx;
    __syncthreads();
    mx = red[0];
#pragma unroll
    for (int w = 1; w < 8; w++) mx = fmaxf(mx, red[w]);
    __syncthreads();

    float s = 0.0f;
#pragma unroll
    for (int i = 0; i < 9; i++) { v[i] = expf(v[i] - mx); s += v[i]; }
#pragma unroll
    for (int o = 16; o > 0; o >>= 1) s += __shfl_xor_sync(0xffffffffu, s, o);
    if ((tid & 31) == 0) red[tid >> 5] = s;
    __syncthreads();
    s = ((red[0] + red[1]) + (red[2] + red[3])) + ((red[4] + red[5]) + (red[6] + red[7]));
    float inv = 1.0f / s;

    size_t o0 = (size_t)blockIdx.x * LSEQ + tid;
#pragma unroll
    for (int i = 0; i < 9; i++) {
        float p = v[i] * inv;
        fp16 h, l; split2(p, h, l);
        ph[o0 + i * 256] = h; pl[o0 + i * 256] = l;
    }
}

// ===========================================================================
// V (L,F) hi -> VT (F,L) per batch
// ===========================================================================
__global__ __launch_bounds__(256) void vtrans(const fp16* __restrict__ ih,
                                              fp16* __restrict__ oh)
{
    __shared__ fp16 t[32][34];
    const int z = blockIdx.z;
    const size_t base = (size_t)z * LSEQ * FD;
    const int f0 = blockIdx.x * 32, l0 = blockIdx.y * 32;
    const int xx = threadIdx.x & 31, yy = threadIdx.x >> 5;

#pragma unroll
    for (int i = 0; i < 32; i += 8)
        t[yy + i][xx] = ih[base + (size_t)(l0 + yy + i) * FD + f0 + xx];
    __syncthreads();
#pragma unroll
    for (int i = 0; i < 32; i += 8)
        oh[base + (size_t)(f0 + yy + i) * LSEQ + l0 + xx] = t[xx][yy + i];
}

// ===========================================================================
extern "C" void kernel_launch(void* const* d_in, const int* in_sizes, int n_in,
                              void* d_out, int out_size)
{
    const float* x  = (const float*)d_in[0];
    const float* Wq = (const float*)d_in[1];
    const float* bq = (const float*)d_in[2];
    const float* Wk = (const float*)d_in[3];
    const float* bk = (const float*)d_in[4];
    const float* Wv = (const float*)d_in[5];
    const float* bv = (const float*)d_in[6];
    float* out = (float*)d_out;

    fp16 *pFh, *pFl, *pWh, *pQh, *pQl, *pKh, *pVh, *pVTh, *pPh, *pPl;
    float* pS;
    cudaGetSymbolAddress((void**)&pFh,  g_flat_h);
    cudaGetSymbolAddress((void**)&pFl,  g_flat_l);
    cudaGetSymbolAddress((void**)&pWh,  g_Wh);
    cudaGetSymbolAddress((void**)&pQh,  g_Qh);
    cudaGetSymbolAddress((void**)&pQl,  g_Ql);
    cudaGetSymbolAddress((void**)&pKh,  g_Kh);
    cudaGetSymbolAddress((void**)&pVh,  g_Vh);
    cudaGetSymbolAddress((void**)&pVTh, g_VTh);
    cudaGetSymbolAddress((void**)&pPh,  g_Ph);
    cudaGetSymbolAddress((void**)&pPl,  g_Pl);
    cudaGetSymbolAddress((void**)&pS,   g_S);

    cudaFuncSetAttribute((const void*)gemm2<0>, cudaFuncAttributeMaxDynamicSharedMemorySize, GEMM_SMEM);
    cudaFuncSetAttribute((const void*)gemm2<1>, cudaFuncAttributeMaxDynamicSharedMemorySize, GEMM_SMEM);
    cudaFuncSetAttribute((const void*)gemm2<2>, cudaFuncAttributeMaxDynamicSharedMemorySize, GEMM_SMEM);

    const int WN = FD * DIM;
    float* qraw = pS;            // raw QKV staged in g_S (42.5M floats >= 3*MF)
    float* kraw = pS + MF;
    float* vraw = pS + 2 * MF;

    // 1) transpose+split x, round weights
    xsplit<<<dim3(LSEQ / 32, DIM / 32, NB), 256>>>(x, pFh, pFl);
    wsplit<<<dim3((WN + 255) / 256, 3), 256>>>(Wq, Wk, Wv, pWh);

    // 2) projections -> raw fp32 (tanh applied); 2-term: (xh+xl)*Wh
    gemm2<0><<<dim3(FD / 128, MTOT / 128, 1), 256, GEMM_SMEM>>>(
        pFh, pFl, pWh + 0 * WN, qraw, bq, DIM, FD, 0, 0, 0, 0.f);
    gemm2<0><<<dim3(FD / 128, MTOT / 128, 1), 256, GEMM_SMEM>>>(
        pFh, pFl, pWh + 1 * WN, kraw, bk, DIM, FD, 0, 0, 0, 0.f);
    gemm2<0><<<dim3(FD / 128, MTOT / 128, 1), 256, GEMM_SMEM>>>(
        pFh, pFl, pWh + 2 * WN, vraw, bv, DIM, FD, 0, 0, 0, 0.f);

    // 3) double inorm + split (Q hi+lo; K,V hi only)
    inorm_split<<<dim3(MTOT, 3), 128>>>(qraw, pQh, pQl, pKh, pVh);

    // 4) V -> VT (hi only)
    vtrans<<<dim3(FD / 32, LSEQ / 32, NB), 256>>>(pVh, pVTh);

    // 5) scores = (Q K^T) * scale; 2-term: (qh+ql)*kh
    gemm2<1><<<dim3(LSEQ / 128, LSEQ / 128, NB), 256, GEMM_SMEM>>>(
        pQh, pQl, pKh, pS, nullptr, FD, LSEQ,
        (long long)LSEQ * FD, (long long)LSEQ * FD, (long long)LSEQ * LSEQ, SCORE_SCALE);

    // 6) softmax + split
    softmax_split<<<NB * LSEQ, 256>>>(pS, pPh, pPl);

    // 7) out = P @ V; 2-term: (ph+pl)*vh
    gemm2<2><<<dim3(FD / 128, LSEQ / 128, NB), 256, GEMM_SMEM>>>(
        pPh, pPl, pVTh, out, nullptr, LSEQ, FD,
        (long long)LSEQ * LSEQ, (long long)FD * LSEQ, (long long)LSEQ * FD, 1.f);
}

// round 8
// speedup vs baseline: 1.5192x; 1.5192x over previous
#include <cuda_runtime.h>
#include <cuda_fp16.h>
#include <cstdint>

#define NB    8
#define DIM   512
#define LSEQ  2304
#define FD    512
#define MTOT  (NB * LSEQ)         // 18432
#define MF    ((size_t)MTOT * FD) // 9437184
#define EPSN  1e-5f
#define SCORE_SCALE 0.044194173824159216f   // 1/sqrt(512)

typedef __half fp16;

// ---------------- scratch (device globals) ----------------
__device__ fp16  g_flat_h[MF], g_flat_l[MF];         // x^T hi/lo (A of proj)
__device__ fp16  g_Wh[3][FD * DIM];                  // W rounded once
__device__ fp16  g_Qh[MF];                           // single fp16 post-inorm
__device__ fp16  g_Kh[MF];
__device__ fp16  g_Vh[MF];
__device__ fp16  g_VTh[MF];                          // V^T per batch (F, L)
__device__ fp16  g_Ph[(size_t)NB * LSEQ * LSEQ];     // probs, single fp16
__device__ float g_S[(size_t)NB * LSEQ * LSEQ];      // scores fp32; front 3*MF floats = raw QKV

// ---------------- PTX helpers (plain sm_80+ target only) ----------------
__device__ __forceinline__ uint32_t smem_u32(const void* p) {
    uint32_t a;
    asm("{ .reg .u64 t; cvta.to.shared.u64 t, %1; cvt.u32.u64 %0, t; }" : "=r"(a) : "l"(p));
    return a;
}
__device__ __forceinline__ void cp16(uint32_t dst, const void* src) {
    asm volatile("cp.async.cg.shared.global [%0], [%1], 16;" :: "r"(dst), "l"(src));
}
#define CP_COMMIT() asm volatile("cp.async.commit_group;" ::: "memory")
#define CP_WAIT(N)  asm volatile("cp.async.wait_group %0;" :: "n"(N) : "memory")

__device__ __forceinline__ void ldsm4(uint32_t* r, uint32_t addr) {
    asm volatile("ldmatrix.sync.aligned.m8n8.x4.shared.b16 {%0,%1,%2,%3}, [%4];"
                 : "=r"(r[0]), "=r"(r[1]), "=r"(r[2]), "=r"(r[3]) : "r"(addr));
}
__device__ __forceinline__ void mma16816(float* c, const uint32_t* a, const uint32_t* b) {
    asm volatile("mma.sync.aligned.m16n8k16.row.col.f32.f16.f16.f32 "
                 "{%0,%1,%2,%3}, {%4,%5,%6,%7}, {%8,%9}, {%0,%1,%2,%3};"
                 : "+f"(c[0]), "+f"(c[1]), "+f"(c[2]), "+f"(c[3])
                 : "r"(a[0]), "r"(a[1]), "r"(a[2]), "r"(a[3]), "r"(b[0]), "r"(b[1]));
}

__device__ __forceinline__ void split2(float v, fp16& h, fp16& l) {
    h = __float2half_rn(v);
    l = __float2half_rn(v - __half2float(h));
}

// ---------------- SMEM geometry ----------------
// tile: 128 rows x 64 fp16 = 128B/row, XOR-swizzled (no pad) = 16384 B
#define TB 16384

// ===========================================================================
// Split-fp16 GEMM, fp32 accum: C[m,n] = sum_k (Ah [+Al])[m,k] * Bh[n,k]
// NT=2: two MMA terms (ah*bh + al*bh). NT=1: single term, no Al tile at all.
// A,B K-major with ld == K. EPI: 0 = tanh(acc+bias), 1 = acc*scale, 2 = none
// ===========================================================================
template <int EPI, int NT>
__global__ void __launch_bounds__(256, 2) gemmN(
    const fp16* __restrict__ Ah, const fp16* __restrict__ Al,
    const fp16* __restrict__ Bh,
    float* __restrict__ C, const float* __restrict__ bias,
    int K, int ldc,
    long long sA, long long sB, long long sC, float scale)
{
    constexpr int NTILES = NT + 1;          // Ah [, Al], Bh
    constexpr int STAGEB = NTILES * TB;
    constexpr int BOFF   = NT * TB;         // byte offset of Bh tile within stage

    extern __shared__ char smem[];
    const uint32_t sbase = smem_u32(smem);
    const int tid  = threadIdx.x;
    const int lane = tid & 31, wid = tid >> 5;
    const int wm = wid >> 2, wn = wid & 3;

    const int m0 = blockIdx.y * 128;
    const int f0 = blockIdx.x * 128;
    Ah += (long long)blockIdx.z * sA + (size_t)m0 * K;
    if (NT == 2) Al += (long long)blockIdx.z * sA + (size_t)m0 * K;
    Bh += (long long)blockIdx.z * sB + (size_t)f0 * K;
    C  += (long long)blockIdx.z * sC;

    // cp.async mapping: thread t -> row r = t>>1, chunks (t&1)*4 + q
    const int ldrow  = tid >> 1;
    const int ldcb   = (tid & 1) * 4;
    const int ldxor  = ldrow & 7;
    const size_t gA0 = (size_t)ldrow * K + ldcb * 8;
    const uint32_t ldRow128 = (uint32_t)(ldrow * 128);

    // ldmatrix mapping (loop-invariant: precompute all 4 phys chunk offsets)
    const int j = lane & 7, g = lane >> 3;
    const int aColSel = g >> 1, bColSel = g & 1;
    const uint32_t aRowB = (uint32_t)((wm * 64 + (g & 1) * 8 + j) * 128);
    const uint32_t bRowB = (uint32_t)((wn * 32 + (g >> 1) * 8 + j) * 128);
    uint32_t aPhys[4], bPhys[4];
#pragma unroll
    for (int c = 0; c < 4; ++c) {
        aPhys[c] = (uint32_t)((((2 * c) + aColSel) ^ j) * 16);
        bPhys[c] = (uint32_t)((((2 * c) + bColSel) ^ j) * 16);
    }

    float acc[4][4][4];
#pragma unroll
    for (int a = 0; a < 4; a++)
#pragma unroll
        for (int b = 0; b < 4; b++)
#pragma unroll
            for (int r = 0; r < 4; r++) acc[a][b][r] = 0.0f;

    const int NIT = K >> 6;   // K / 64

    auto load_stage = [&](int st, int k0) {
        const uint32_t base = sbase + st * STAGEB + ldRow128;
#pragma unroll
        for (int q = 0; q < 4; ++q) {
            const int c16 = ldcb + q;
            const uint32_t d = base + (uint32_t)((c16 ^ ldxor) * 16);
            cp16(d,        Ah + gA0 + k0 + q * 8);
            if (NT == 2) cp16(d + TB, Al + gA0 + k0 + q * 8);
            cp16(d + BOFF, Bh + gA0 + k0 + q * 8);   // gB0 == gA0 since ld == K
        }
    };

    load_stage(0, 0);
    CP_COMMIT();
    if (NIT > 1) load_stage(1, 64);
    CP_COMMIT();

    for (int it = 0; it < NIT; ++it) {
        CP_WAIT(1);
        __syncthreads();
        const uint32_t sb = sbase + (it & 1) * STAGEB;
#pragma unroll
        for (int c = 0; c < 4; ++c) {          // four k16 blocks per stage
            uint32_t bh[8];
            ldsm4(bh,     sb + BOFF + bRowB + bPhys[c]);
            ldsm4(bh + 4, sb + BOFF + bRowB + 16 * 128 + bPhys[c]);
#pragma unroll
            for (int mi = 0; mi < 4; ++mi) {
                uint32_t ah[4];
                ldsm4(ah, sb + aRowB + mi * (16 * 128) + aPhys[c]);
#pragma unroll
                for (int ni = 0; ni < 4; ++ni) mma16816(acc[mi][ni], ah, &bh[ni * 2]);
                if (NT == 2) {
                    uint32_t al[4];
                    ldsm4(al, sb + TB + aRowB + mi * (16 * 128) + aPhys[c]);
#pragma unroll
                    for (int ni = 0; ni < 4; ++ni) mma16816(acc[mi][ni], al, &bh[ni * 2]);
                }
            }
        }
        __syncthreads();
        if (it + 2 < NIT) load_stage(it & 1, (it + 2) * 64);
        CP_COMMIT();
    }

    // epilogue
    const int qp = lane & 3, rr = lane >> 2;
#pragma unroll
    for (int mi = 0; mi < 4; ++mi) {
#pragma unroll
        for (int ni = 0; ni < 4; ++ni) {
            const int row = m0 + wm * 64 + mi * 16 + rr;
            const int col = f0 + wn * 32 + ni * 8 + qp * 2;
            float2 v0 = make_float2(acc[mi][ni][0], acc[mi][ni][1]);
            float2 v1 = make_float2(acc[mi][ni][2], acc[mi][ni][3]);
            if (EPI == 0) {
                float2 b = *(const float2*)(bias + col);
                v0.x = tanhf(v0.x + b.x); v0.y = tanhf(v0.y + b.y);
                v1.x = tanhf(v1.x + b.x); v1.y = tanhf(v1.y + b.y);
            } else if (EPI == 1) {
                v0.x *= scale; v0.y *= scale; v1.x *= scale; v1.y *= scale;
            }
            *(float2*)(C + (size_t)row * ldc + col)       = v0;
            *(float2*)(C + (size_t)(row + 8) * ldc + col) = v1;
        }
    }
}

// ===========================================================================
// x (N,D,L) -> flat hi/lo (M,D) fp16 (transpose + split)
// ===========================================================================
__global__ __launch_bounds__(256) void xsplit(const float* __restrict__ x,
                                              fp16* __restrict__ oh, fp16* __restrict__ ol)
{
    __shared__ float t[32][33];
    const int z = blockIdx.z;
    const float* in = x + (size_t)z * DIM * LSEQ;
    const int l0 = blockIdx.x * 32, d0 = blockIdx.y * 32;
    const int xx = threadIdx.x & 31, yy = threadIdx.x >> 5;
#pragma unroll
    for (int i = 0; i < 32; i += 8)
        t[yy + i][xx] = in[(size_t)(d0 + yy + i) * LSEQ + l0 + xx];
    __syncthreads();
#pragma unroll
    for (int i = 0; i < 32; i += 8) {
        float v = t[xx][yy + i];
        size_t o = (size_t)(z * LSEQ + l0 + yy + i) * DIM + d0 + xx;
        fp16 h, l; split2(v, h, l);
        oh[o] = h; ol[o] = l;
    }
}

// weights: round once to fp16; grid.y selects q/k/v
__global__ __launch_bounds__(256) void wsplit(const float* __restrict__ wq,
                                              const float* __restrict__ wk,
                                              const float* __restrict__ wv,
                                              fp16* __restrict__ h)
{
    const int n = FD * DIM;
    const float* w = (blockIdx.y == 0) ? wq : (blockIdx.y == 1) ? wk : wv;
    int i = blockIdx.x * 256 + threadIdx.x;
    if (i < n) h[blockIdx.y * n + i] = __float2half_rn(w[i]);
}

// ===========================================================================
// double instance norm: raw fp32 row -> single fp16 row (grid.y = q/k/v)
// ===========================================================================
__device__ __forceinline__ float rsum128(float x, volatile float* red, int tid)
{
#pragma unroll
    for (int o = 16; o > 0; o >>= 1) x += __shfl_down_sync(0xffffffffu, x, o);
    if ((tid & 31) == 0) red[tid >> 5] = x;
    __syncthreads();
    float t = (red[0] + red[1]) + (red[2] + red[3]);
    __syncthreads();
    return t;
}

__global__ __launch_bounds__(128) void inorm_half(const float* __restrict__ raw,
                                                  fp16* __restrict__ qh,
                                                  fp16* __restrict__ kh,
                                                  fp16* __restrict__ vh)
{
    const int which = blockIdx.y;
    raw += (size_t)which * MF;
    fp16* oh = (which == 0) ? qh : (which == 1) ? kh : vh;

    const float4* row = (const float4*)(raw + (size_t)blockIdx.x * FD);
    __shared__ float red[4];
    const int tid = threadIdx.x;
    float4 v = row[tid];

    float s  = rsum128(v.x + v.y + v.z + v.w, red, tid);
    float mu = s * (1.0f / FD);
    v.x -= mu; v.y -= mu; v.z -= mu; v.w -= mu;
    float sq = rsum128(v.x * v.x + v.y * v.y + v.z * v.z + v.w * v.w, red, tid);
    float r1 = rsqrtf(sq * (1.0f / FD) + EPSN);
    v.x *= r1; v.y *= r1; v.z *= r1; v.w *= r1;

    float s2  = rsum128(v.x + v.y + v.z + v.w, red, tid);
    float mu2 = s2 * (1.0f / FD);
    v.x -= mu2; v.y -= mu2; v.z -= mu2; v.w -= mu2;
    float sq2 = rsum128(v.x * v.x + v.y * v.y + v.z * v.z + v.w * v.w, red, tid);
    float r2  = rsqrtf(sq2 * (1.0f / FD) + EPSN);
    v.x *= r2; v.y *= r2; v.z *= r2; v.w *= r2;

    __half2* o2 = (__half2*)(oh + (size_t)blockIdx.x * FD + tid * 4);
    o2[0] = __floats2half2_rn(v.x, v.y);
    o2[1] = __floats2half2_rn(v.z, v.w);
}

// ===========================================================================
// softmax: fp32 scores row -> single fp16 prob row
// ===========================================================================
__global__ __launch_bounds__(256) void softmax_half(const float* __restrict__ S,
                                                    fp16* __restrict__ ph)
{
    const float* row = S + (size_t)blockIdx.x * LSEQ;
    __shared__ float red[8];
    const int tid = threadIdx.x;

    float v[9];
    float mx = -1e30f;
#pragma unroll
    for (int i = 0; i < 9; i++) { v[i] = row[tid + i * 256]; mx = fmaxf(mx, v[i]); }
#pragma unroll
    for (int o = 16; o > 0; o >>= 1) mx = fmaxf(mx, __shfl_xor_sync(0xffffffffu, mx, o));
    if ((tid & 31) == 0) red[tid >> 5] = mx;
    __syncthreads();
    mx = red[0];
#pragma unroll
    for (int w = 1; w < 8; w++) mx = fmaxf(mx, red[w]);
    __syncthreads();

    float s = 0.0f;
#pragma unroll
    for (int i = 0; i < 9; i++) { v[i] = expf(v[i] - mx); s += v[i]; }
#pragma unroll
    for (int o = 16; o > 0; o >>= 1) s += __shfl_xor_sync(0xffffffffu, s, o);
    if ((tid & 31) == 0) red[tid >> 5] = s;
    __syncthreads();
    s = ((red[0] + red[1]) + (red[2] + red[3])) + ((red[4] + red[5]) + (red[6] + red[7]));
    float inv = 1.0f / s;

    size_t o0 = (size_t)blockIdx.x * LSEQ + tid;
#pragma unroll
    for (int i = 0; i < 9; i++)
        ph[o0 + i * 256] = __float2half_rn(v[i] * inv);
}

// ===========================================================================
// V (L,F) -> VT (F,L) per batch
// ===========================================================================
__global__ __launch_bounds__(256) void vtrans(const fp16* __restrict__ ih,
                                              fp16* __restrict__ oh)
{
    __shared__ fp16 t[32][34];
    const int z = blockIdx.z;
    const size_t base = (size_t)z * LSEQ * FD;
    const int f0 = blockIdx.x * 32, l0 = blockIdx.y * 32;
    const int xx = threadIdx.x & 31, yy = threadIdx.x >> 5;

#pragma unroll
    for (int i = 0; i < 32; i += 8)
        t[yy + i][xx] = ih[base + (size_t)(l0 + yy + i) * FD + f0 + xx];
    __syncthreads();
#pragma unroll
    for (int i = 0; i < 32; i += 8)
        oh[base + (size_t)(f0 + yy + i) * LSEQ + l0 + xx] = t[xx][yy + i];
}

// ===========================================================================
extern "C" void kernel_launch(void* const* d_in, const int* in_sizes, int n_in,
                              void* d_out, int out_size)
{
    const float* x  = (const float*)d_in[0];
    const float* Wq = (const float*)d_in[1];
    const float* bq = (const float*)d_in[2];
    const float* Wk = (const float*)d_in[3];
    const float* bk = (const float*)d_in[4];
    const float* Wv = (const float*)d_in[5];
    const float* bv = (const float*)d_in[6];
    float* out = (float*)d_out;

    fp16 *pFh, *pFl, *pWh, *pQh, *pKh, *pVh, *pVTh, *pPh;
    float* pS;
    cudaGetSymbolAddress((void**)&pFh,  g_flat_h);
    cudaGetSymbolAddress((void**)&pFl,  g_flat_l);
    cudaGetSymbolAddress((void**)&pWh,  g_Wh);
    cudaGetSymbolAddress((void**)&pQh,  g_Qh);
    cudaGetSymbolAddress((void**)&pKh,  g_Kh);
    cudaGetSymbolAddress((void**)&pVh,  g_Vh);
    cudaGetSymbolAddress((void**)&pVTh, g_VTh);
    cudaGetSymbolAddress((void**)&pPh,  g_Ph);
    cudaGetSymbolAddress((void**)&pS,   g_S);

    const int SM2 = 2 * 3 * TB;   // NT=2: 96 KB
    const int SM1 = 2 * 2 * TB;   // NT=1: 64 KB
    cudaFuncSetAttribute((const void*)gemmN<0, 2>, cudaFuncAttributeMaxDynamicSharedMemorySize, SM2);
    cudaFuncSetAttribute((const void*)gemmN<1, 1>, cudaFuncAttributeMaxDynamicSharedMemorySize, SM1);
    cudaFuncSetAttribute((const void*)gemmN<2, 1>, cudaFuncAttributeMaxDynamicSharedMemorySize, SM1);

    const int WN = FD * DIM;
    float* qraw = pS;            // raw QKV staged in g_S (42.5M floats >= 3*MF)
    float* kraw = pS + MF;
    float* vraw = pS + 2 * MF;

    // 1) transpose+split x, round weights
    xsplit<<<dim3(LSEQ / 32, DIM / 32, NB), 256>>>(x, pFh, pFl);
    wsplit<<<dim3((WN + 255) / 256, 3), 256>>>(Wq, Wk, Wv, pWh);

    // 2) projections -> raw fp32 (tanh applied); 2-term: (xh+xl)*Wh
    gemmN<0, 2><<<dim3(FD / 128, MTOT / 128, 1), 256, SM2>>>(
        pFh, pFl, pWh + 0 * WN, qraw, bq, DIM, FD, 0, 0, 0, 0.f);
    gemmN<0, 2><<<dim3(FD / 128, MTOT / 128, 1), 256, SM2>>>(
        pFh, pFl, pWh + 1 * WN, kraw, bk, DIM, FD, 0, 0, 0, 0.f);
    gemmN<0, 2><<<dim3(FD / 128, MTOT / 128, 1), 256, SM2>>>(
        pFh, pFl, pWh + 2 * WN, vraw, bv, DIM, FD, 0, 0, 0, 0.f);

    // 3) double inorm -> single fp16 Q/K/V
    inorm_half<<<dim3(MTOT, 3), 128>>>(qraw, pQh, pKh, pVh);

    // 4) V -> VT
    vtrans<<<dim3(FD / 32, LSEQ / 32, NB), 256>>>(pVh, pVTh);

    // 5) scores = (Q K^T) * scale; 1-term qh*kh
    gemmN<1, 1><<<dim3(LSEQ / 128, LSEQ / 128, NB), 256, SM1>>>(
        pQh, nullptr, pKh, pS, nullptr, FD, LSEQ,
        (long long)LSEQ * FD, (long long)LSEQ * FD, (long long)LSEQ * LSEQ, SCORE_SCALE);

    // 6) softmax -> single fp16 P
    softmax_half<<<NB * LSEQ, 256>>>(pS, pPh);

    // 7) out = P @ V; 1-term ph*vh
    gemmN<2, 1><<<dim3(FD / 128, LSEQ / 128, NB), 256, SM1>>>(
        pPh, nullptr, pVTh, out, nullptr, LSEQ, FD,
        (long long)LSEQ * LSEQ, (long long)FD * LSEQ, (long long)LSEQ * FD, 1.f);
}

// round 9
// speedup vs baseline: 1.7299x; 1.1387x over previous
#include <cuda_runtime.h>
#include <cuda_fp16.h>
#include <cstdint>

#define NB    8
#define DIM   512
#define LSEQ  2304
#define FD    512
#define MTOT  (NB * LSEQ)         // 18432
#define MF    ((size_t)MTOT * FD) // 9437184
#define EPSN  1e-5f
#define SCORE_SCALE 0.044194173824159216f   // 1/sqrt(512)

typedef __half fp16;

// ---------------- scratch (device globals) ----------------
__device__ fp16  g_flat_h[MF];                       // x^T rounded once (A of proj)
__device__ fp16  g_Wh[3][FD * DIM];                  // W rounded once
__device__ fp16  g_Qh[MF];                           // single fp16 post-inorm
__device__ fp16  g_Kh[MF];
__device__ fp16  g_Vh[MF];
__device__ fp16  g_VTh[MF];                          // V^T per batch (F, L)
__device__ fp16  g_Ph[(size_t)NB * LSEQ * LSEQ];     // probs, single fp16
__device__ float g_S[(size_t)NB * LSEQ * LSEQ];      // scores fp32; front 3*MF floats = raw QKV

// ---------------- PTX helpers (plain sm_80+ target only) ----------------
__device__ __forceinline__ uint32_t smem_u32(const void* p) {
    uint32_t a;
    asm("{ .reg .u64 t; cvta.to.shared.u64 t, %1; cvt.u32.u64 %0, t; }" : "=r"(a) : "l"(p));
    return a;
}
__device__ __forceinline__ void cp16(uint32_t dst, const void* src) {
    asm volatile("cp.async.cg.shared.global [%0], [%1], 16;" :: "r"(dst), "l"(src));
}
#define CP_COMMIT() asm volatile("cp.async.commit_group;" ::: "memory")
#define CP_WAIT(N)  asm volatile("cp.async.wait_group %0;" :: "n"(N) : "memory")

__device__ __forceinline__ void ldsm4(uint32_t* r, uint32_t addr) {
    asm volatile("ldmatrix.sync.aligned.m8n8.x4.shared.b16 {%0,%1,%2,%3}, [%4];"
                 : "=r"(r[0]), "=r"(r[1]), "=r"(r[2]), "=r"(r[3]) : "r"(addr));
}
__device__ __forceinline__ void mma16816(float* c, const uint32_t* a, const uint32_t* b) {
    asm volatile("mma.sync.aligned.m16n8k16.row.col.f32.f16.f16.f32 "
                 "{%0,%1,%2,%3}, {%4,%5,%6,%7}, {%8,%9}, {%0,%1,%2,%3};"
                 : "+f"(c[0]), "+f"(c[1]), "+f"(c[2]), "+f"(c[3])
                 : "r"(a[0]), "r"(a[1]), "r"(a[2]), "r"(a[3]), "r"(b[0]), "r"(b[1]));
}

// ---------------- SMEM geometry ----------------
// tile: 128 rows x 64 fp16 = 128B/row, XOR-swizzled (no pad) = 16384 B
#define TB 16384
#define STAGEB (2 * TB)           // Ah | Bh
#define GEMM_SMEM (2 * STAGEB)    // 64 KB

// ===========================================================================
// 1-term fp16 GEMM, fp32 accum: C[m,n] = sum_k A[m,k] * B[n,k]
// A,B K-major with ld == K.
// EPI: 0 = tanh(acc+bias), selecting bias by blockIdx.z; 1 = acc*scale; 2 = none
// ===========================================================================
template <int EPI>
__global__ void __launch_bounds__(256, 2) gemm1(
    const fp16* __restrict__ A, const fp16* __restrict__ B,
    float* __restrict__ C,
    const float* __restrict__ b0, const float* __restrict__ b1,
    const float* __restrict__ b2,
    int K, int ldc,
    long long sA, long long sB, long long sC, float scale)
{
    extern __shared__ char smem[];
    const uint32_t sbase = smem_u32(smem);
    const int tid  = threadIdx.x;
    const int lane = tid & 31, wid = tid >> 5;
    const int wm = wid >> 2, wn = wid & 3;

    const int m0 = blockIdx.y * 128;
    const int f0 = blockIdx.x * 128;
    A += (long long)blockIdx.z * sA + (size_t)m0 * K;
    B += (long long)blockIdx.z * sB + (size_t)f0 * K;
    C += (long long)blockIdx.z * sC;
    const float* bias = (EPI == 0)
        ? ((blockIdx.z == 0) ? b0 : (blockIdx.z == 1) ? b1 : b2) : nullptr;

    // cp.async mapping: thread t -> row r = t>>1, chunks (t&1)*4 + q
    const int ldrow  = tid >> 1;
    const int ldcb   = (tid & 1) * 4;
    const int ldxor  = ldrow & 7;
    const size_t gA0 = (size_t)ldrow * K + ldcb * 8;
    const uint32_t ldRow128 = (uint32_t)(ldrow * 128);

    // ldmatrix mapping (loop-invariant phys offsets)
    const int j = lane & 7, g = lane >> 3;
    const int aColSel = g >> 1, bColSel = g & 1;
    const uint32_t aRowB = (uint32_t)((wm * 64 + (g & 1) * 8 + j) * 128);
    const uint32_t bRowB = (uint32_t)((wn * 32 + (g >> 1) * 8 + j) * 128);
    uint32_t aPhys[4], bPhys[4];
#pragma unroll
    for (int c = 0; c < 4; ++c) {
        aPhys[c] = (uint32_t)((((2 * c) + aColSel) ^ j) * 16);
        bPhys[c] = (uint32_t)((((2 * c) + bColSel) ^ j) * 16);
    }

    float acc[4][4][4];
#pragma unroll
    for (int a = 0; a < 4; a++)
#pragma unroll
        for (int b = 0; b < 4; b++)
#pragma unroll
            for (int r = 0; r < 4; r++) acc[a][b][r] = 0.0f;

    const int NIT = K >> 6;   // K / 64

    auto load_stage = [&](int st, int k0) {
        const uint32_t base = sbase + st * STAGEB + ldRow128;
#pragma unroll
        for (int q = 0; q < 4; ++q) {
            const int c16 = ldcb + q;
            const uint32_t d = base + (uint32_t)((c16 ^ ldxor) * 16);
            cp16(d,      A + gA0 + k0 + q * 8);
            cp16(d + TB, B + gA0 + k0 + q * 8);   // gB0 == gA0 since ld == K
        }
    };

    load_stage(0, 0);
    CP_COMMIT();
    if (NIT > 1) load_stage(1, 64);
    CP_COMMIT();

    for (int it = 0; it < NIT; ++it) {
        CP_WAIT(1);
        __syncthreads();
        const uint32_t sb = sbase + (it & 1) * STAGEB;
#pragma unroll
        for (int c = 0; c < 4; ++c) {          // four k16 blocks per stage
            uint32_t bh[8];
            ldsm4(bh,     sb + TB + bRowB + bPhys[c]);
            ldsm4(bh + 4, sb + TB + bRowB + 16 * 128 + bPhys[c]);
#pragma unroll
            for (int mi = 0; mi < 4; ++mi) {
                uint32_t ah[4];
                ldsm4(ah, sb + aRowB + mi * (16 * 128) + aPhys[c]);
#pragma unroll
                for (int ni = 0; ni < 4; ++ni) mma16816(acc[mi][ni], ah, &bh[ni * 2]);
            }
        }
        __syncthreads();
        if (it + 2 < NIT) load_stage(it & 1, (it + 2) * 64);
        CP_COMMIT();
    }

    // epilogue
    const int qp = lane & 3, rr = lane >> 2;
#pragma unroll
    for (int mi = 0; mi < 4; ++mi) {
#pragma unroll
        for (int ni = 0; ni < 4; ++ni) {
            const int row = m0 + wm * 64 + mi * 16 + rr;
            const int col = f0 + wn * 32 + ni * 8 + qp * 2;
            float2 v0 = make_float2(acc[mi][ni][0], acc[mi][ni][1]);
            float2 v1 = make_float2(acc[mi][ni][2], acc[mi][ni][3]);
            if (EPI == 0) {
                float2 b = *(const float2*)(bias + col);
                v0.x = tanhf(v0.x + b.x); v0.y = tanhf(v0.y + b.y);
                v1.x = tanhf(v1.x + b.x); v1.y = tanhf(v1.y + b.y);
            } else if (EPI == 1) {
                v0.x *= scale; v0.y *= scale; v1.x *= scale; v1.y *= scale;
            }
            *(float2*)(C + (size_t)row * ldc + col)       = v0;
            *(float2*)(C + (size_t)(row + 8) * ldc + col) = v1;
        }
    }
}

// ===========================================================================
// x (N,D,L) -> flat (M,D) fp16 rounded once (transpose)
// ===========================================================================
__global__ __launch_bounds__(256) void xhalf(const float* __restrict__ x,
                                             fp16* __restrict__ oh)
{
    __shared__ float t[32][33];
    const int z = blockIdx.z;
    const float* in = x + (size_t)z * DIM * LSEQ;
    const int l0 = blockIdx.x * 32, d0 = blockIdx.y * 32;
    const int xx = threadIdx.x & 31, yy = threadIdx.x >> 5;
#pragma unroll
    for (int i = 0; i < 32; i += 8)
        t[yy + i][xx] = in[(size_t)(d0 + yy + i) * LSEQ + l0 + xx];
    __syncthreads();
#pragma unroll
    for (int i = 0; i < 32; i += 8) {
        size_t o = (size_t)(z * LSEQ + l0 + yy + i) * DIM + d0 + xx;
        oh[o] = __float2half_rn(t[xx][yy + i]);
    }
}

// weights: round once to fp16; grid.y selects q/k/v
__global__ __launch_bounds__(256) void wsplit(const float* __restrict__ wq,
                                              const float* __restrict__ wk,
                                              const float* __restrict__ wv,
                                              fp16* __restrict__ h)
{
    const int n = FD * DIM;
    const float* w = (blockIdx.y == 0) ? wq : (blockIdx.y == 1) ? wk : wv;
    int i = blockIdx.x * 256 + threadIdx.x;
    if (i < n) h[blockIdx.y * n + i] = __float2half_rn(w[i]);
}

// ===========================================================================
// double instance norm: raw fp32 row -> single fp16 row (grid.y = q/k/v)
// ===========================================================================
__device__ __forceinline__ float rsum128(float x, volatile float* red, int tid)
{
#pragma unroll
    for (int o = 16; o > 0; o >>= 1) x += __shfl_down_sync(0xffffffffu, x, o);
    if ((tid & 31) == 0) red[tid >> 5] = x;
    __syncthreads();
    float t = (red[0] + red[1]) + (red[2] + red[3]);
    __syncthreads();
    return t;
}

__global__ __launch_bounds__(128) void inorm_half(const float* __restrict__ raw,
                                                  fp16* __restrict__ qh,
                                                  fp16* __restrict__ kh,
                                                  fp16* __restrict__ vh)
{
    const int which = blockIdx.y;
    raw += (size_t)which * MF;
    fp16* oh = (which == 0) ? qh : (which == 1) ? kh : vh;

    const float4* row = (const float4*)(raw + (size_t)blockIdx.x * FD);
    __shared__ float red[4];
    const int tid = threadIdx.x;
    float4 v = row[tid];

    float s  = rsum128(v.x + v.y + v.z + v.w, red, tid);
    float mu = s * (1.0f / FD);
    v.x -= mu; v.y -= mu; v.z -= mu; v.w -= mu;
    float sq = rsum128(v.x * v.x + v.y * v.y + v.z * v.z + v.w * v.w, red, tid);
    float r1 = rsqrtf(sq * (1.0f / FD) + EPSN);
    v.x *= r1; v.y *= r1; v.z *= r1; v.w *= r1;

    float s2  = rsum128(v.x + v.y + v.z + v.w, red, tid);
    float mu2 = s2 * (1.0f / FD);
    v.x -= mu2; v.y -= mu2; v.z -= mu2; v.w -= mu2;
    float sq2 = rsum128(v.x * v.x + v.y * v.y + v.z * v.z + v.w * v.w, red, tid);
    float r2  = rsqrtf(sq2 * (1.0f / FD) + EPSN);
    v.x *= r2; v.y *= r2; v.z *= r2; v.w *= r2;

    __half2* o2 = (__half2*)(oh + (size_t)blockIdx.x * FD + tid * 4);
    o2[0] = __floats2half2_rn(v.x, v.y);
    o2[1] = __floats2half2_rn(v.z, v.w);
}

// ===========================================================================
// softmax: fp32 scores row -> single fp16 prob row
// ===========================================================================
__global__ __launch_bounds__(256) void softmax_half(const float* __restrict__ S,
                                                    fp16* __restrict__ ph)
{
    const float* row = S + (size_t)blockIdx.x * LSEQ;
    __shared__ float red[8];
    const int tid = threadIdx.x;

    float v[9];
    float mx = -1e30f;
#pragma unroll
    for (int i = 0; i < 9; i++) { v[i] = row[tid + i * 256]; mx = fmaxf(mx, v[i]); }
#pragma unroll
    for (int o = 16; o > 0; o >>= 1) mx = fmaxf(mx, __shfl_xor_sync(0xffffffffu, mx, o));
    if ((tid & 31) == 0) red[tid >> 5] = mx;
    __syncthreads();
    mx = red[0];
#pragma unroll
    for (int w = 1; w < 8; w++) mx = fmaxf(mx, red[w]);
    __syncthreads();

    float s = 0.0f;
#pragma unroll
    for (int i = 0; i < 9; i++) { v[i] = expf(v[i] - mx); s += v[i]; }
#pragma unroll
    for (int o = 16; o > 0; o >>= 1) s += __shfl_xor_sync(0xffffffffu, s, o);
    if ((tid & 31) == 0) red[tid >> 5] = s;
    __syncthreads();
    s = ((red[0] + red[1]) + (red[2] + red[3])) + ((red[4] + red[5]) + (red[6] + red[7]));
    float inv = 1.0f / s;

    size_t o0 = (size_t)blockIdx.x * LSEQ + tid;
#pragma unroll
    for (int i = 0; i < 9; i++)
        ph[o0 + i * 256] = __float2half_rn(v[i] * inv);
}

// ===========================================================================
// V (L,F) -> VT (F,L) per batch
// ===========================================================================
__global__ __launch_bounds__(256) void vtrans(const fp16* __restrict__ ih,
                                              fp16* __restrict__ oh)
{
    __shared__ fp16 t[32][34];
    const int z = blockIdx.z;
    const size_t base = (size_t)z * LSEQ * FD;
    const int f0 = blockIdx.x * 32, l0 = blockIdx.y * 32;
    const int xx = threadIdx.x & 31, yy = threadIdx.x >> 5;

#pragma unroll
    for (int i = 0; i < 32; i += 8)
        t[yy + i][xx] = ih[base + (size_t)(l0 + yy + i) * FD + f0 + xx];
    __syncthreads();
#pragma unroll
    for (int i = 0; i < 32; i += 8)
        oh[base + (size_t)(f0 + yy + i) * LSEQ + l0 + xx] = t[xx][yy + i];
}

// ===========================================================================
extern "C" void kernel_launch(void* const* d_in, const int* in_sizes, int n_in,
                              void* d_out, int out_size)
{
    const float* x  = (const float*)d_in[0];
    const float* Wq = (const float*)d_in[1];
    const float* bq = (const float*)d_in[2];
    const float* Wk = (const float*)d_in[3];
    const float* bk = (const float*)d_in[4];
    const float* Wv = (const float*)d_in[5];
    const float* bv = (const float*)d_in[6];
    float* out = (float*)d_out;

    fp16 *pFh, *pWh, *pQh, *pKh, *pVh, *pVTh, *pPh;
    float* pS;
    cudaGetSymbolAddress((void**)&pFh,  g_flat_h);
    cudaGetSymbolAddress((void**)&pWh,  g_Wh);
    cudaGetSymbolAddress((void**)&pQh,  g_Qh);
    cudaGetSymbolAddress((void**)&pKh,  g_Kh);
    cudaGetSymbolAddress((void**)&pVh,  g_Vh);
    cudaGetSymbolAddress((void**)&pVTh, g_VTh);
    cudaGetSymbolAddress((void**)&pPh,  g_Ph);
    cudaGetSymbolAddress((void**)&pS,   g_S);

    cudaFuncSetAttribute((const void*)gemm1<0>, cudaFuncAttributeMaxDynamicSharedMemorySize, GEMM_SMEM);
    cudaFuncSetAttribute((const void*)gemm1<1>, cudaFuncAttributeMaxDynamicSharedMemorySize, GEMM_SMEM);
    cudaFuncSetAttribute((const void*)gemm1<2>, cudaFuncAttributeMaxDynamicSharedMemorySize, GEMM_SMEM);

    const int WN = FD * DIM;
    float* qraw = pS;            // raw QKV staged in g_S (42.5M floats >= 3*MF)

    // 1) transpose+round x, round weights
    xhalf<<<dim3(LSEQ / 32, DIM / 32, NB), 256>>>(x, pFh);
    wsplit<<<dim3((WN + 255) / 256, 3), 256>>>(Wq, Wk, Wv, pWh);

    // 2) all three projections in ONE launch (z selects W slice, bias, C slice)
    gemm1<0><<<dim3(FD / 128, MTOT / 128, 3), 256, GEMM_SMEM>>>(
        pFh, pWh, qraw, bq, bk, bv, DIM, FD,
        0, (long long)WN, (long long)MF, 0.f);

    // 3) double inorm -> single fp16 Q/K/V
    inorm_half<<<dim3(MTOT, 3), 128>>>(qraw, pQh, pKh, pVh);

    // 4) V -> VT
    vtrans<<<dim3(FD / 32, LSEQ / 32, NB), 256>>>(pVh, pVTh);

    // 5) scores = (Q K^T) * scale
    gemm1<1><<<dim3(LSEQ / 128, LSEQ / 128, NB), 256, GEMM_SMEM>>>(
        pQh, pKh, pS, nullptr, nullptr, nullptr, FD, LSEQ,
        (long long)LSEQ * FD, (long long)LSEQ * FD, (long long)LSEQ * LSEQ, SCORE_SCALE);

    // 6) softmax -> single fp16 P
    softmax_half<<<NB * LSEQ, 256>>>(pS, pPh);

    // 7) out = P @ V
    gemm1<2><<<dim3(FD / 128, LSEQ / 128, NB), 256, GEMM_SMEM>>>(
        pPh, pVTh, out, nullptr, nullptr, nullptr, LSEQ, FD,
        (long long)LSEQ * LSEQ, (long long)FD * LSEQ, (long long)LSEQ * FD, 1.f);
}

// round 10
// speedup vs baseline: 1.8712x; 1.0817x over previous
#include <cuda_runtime.h>
#include <cuda_fp16.h>
#include <cstdint>

#define NB    8
#define DIM   512
#define LSEQ  2304
#define FD    512
#define MTOT  (NB * LSEQ)         // 18432
#define MF    ((size_t)MTOT * FD) // 9437184
#define EPSN  1e-5f
#define SCORE_SCALE 0.044194173824159216f   // 1/sqrt(512)

typedef __half fp16;

// ---------------- scratch (device globals) ----------------
__device__ fp16  g_flat_h[MF];                       // x^T rounded once
__device__ fp16  g_Wh[3][FD * DIM];                  // W rounded once
__device__ fp16  g_Qh[MF];
__device__ fp16  g_Kh[MF];
__device__ fp16  g_Vh[MF];
__device__ fp16  g_VTh[MF];                          // V^T per batch (F, L)
__device__ fp16  g_Ph[(size_t)NB * LSEQ * LSEQ];     // probs fp16
__device__ float g_S[(size_t)NB * LSEQ * LSEQ];      // scores fp32; front doubles as fp16 raw QKV

// ---------------- PTX helpers ----------------
__device__ __forceinline__ uint32_t smem_u32(const void* p) {
    uint32_t a;
    asm("{ .reg .u64 t; cvta.to.shared.u64 t, %1; cvt.u32.u64 %0, t; }" : "=r"(a) : "l"(p));
    return a;
}
__device__ __forceinline__ void cp16(uint32_t dst, const void* src) {
    asm volatile("cp.async.cg.shared.global [%0], [%1], 16;" :: "r"(dst), "l"(src));
}
#define CP_COMMIT() asm volatile("cp.async.commit_group;" ::: "memory")
#define CP_WAIT(N)  asm volatile("cp.async.wait_group %0;" :: "n"(N) : "memory")

__device__ __forceinline__ void ldsm4(uint32_t* r, uint32_t addr) {
    asm volatile("ldmatrix.sync.aligned.m8n8.x4.shared.b16 {%0,%1,%2,%3}, [%4];"
                 : "=r"(r[0]), "=r"(r[1]), "=r"(r[2]), "=r"(r[3]) : "r"(addr));
}
__device__ __forceinline__ void mma16816(float* c, const uint32_t* a, const uint32_t* b) {
    asm volatile("mma.sync.aligned.m16n8k16.row.col.f32.f16.f16.f32 "
                 "{%0,%1,%2,%3}, {%4,%5,%6,%7}, {%8,%9}, {%0,%1,%2,%3};"
                 : "+f"(c[0]), "+f"(c[1]), "+f"(c[2]), "+f"(c[3])
                 : "r"(a[0]), "r"(a[1]), "r"(a[2]), "r"(a[3]), "r"(b[0]), "r"(b[1]));
}

// ---------------- SMEM geometry ----------------
// tile: 128 rows x 64 fp16 = 128B/row, XOR-swizzled = 16384 B
#define TB 16384
#define STAGEB (2 * TB)           // A | B
#define GEMM_SMEM (2 * STAGEB)    // 64 KB

// ===========================================================================
// 1-term fp16 GEMM, fp32 accum, 512 threads, warp tile 32x32 (high WLP).
// C[m,n] = sum_k A[m,k]*B[n,k]; A,B K-major, ld == K.
// EPI 0: fp16 out = tanh(acc + bias[z]);  EPI 1: fp32 out = acc*scale;
// EPI 2: fp32 out = acc.
// ===========================================================================
template <int EPI>
__global__ void __launch_bounds__(512, 2) gemm1(
    const fp16* __restrict__ A, const fp16* __restrict__ B,
    float* __restrict__ C, fp16* __restrict__ Ch,
    const float* __restrict__ b0, const float* __restrict__ b1,
    const float* __restrict__ b2,
    int K, int ldc,
    long long sA, long long sB, long long sC, float scale)
{
    extern __shared__ char smem[];
    const uint32_t sbase = smem_u32(smem);
    const int tid  = threadIdx.x;
    const int lane = tid & 31, wid = tid >> 5;       // 16 warps
    const int wm = wid >> 2, wn = wid & 3;           // 4m x 4n, warp tile 32x32

    const int m0 = blockIdx.y * 128;
    const int f0 = blockIdx.x * 128;
    A += (long long)blockIdx.z * sA + (size_t)m0 * K;
    B += (long long)blockIdx.z * sB + (size_t)f0 * K;
    if (EPI == 0) Ch += (long long)blockIdx.z * sC;
    else          C  += (long long)blockIdx.z * sC;
    const float* bias = (EPI == 0)
        ? ((blockIdx.z == 0) ? b0 : (blockIdx.z == 1) ? b1 : b2) : nullptr;

    // cp.async mapping: thread t -> row = t>>2, chunk pair = (t&3)*2 + q
    const int ldrow  = tid >> 2;
    const int ldcp   = (tid & 3) * 2;
    const int ldxor  = ldrow & 7;
    const size_t gA0 = (size_t)ldrow * K + ldcp * 8;
    const uint32_t ldRow128 = (uint32_t)(ldrow * 128);

    // ldmatrix lane mapping
    const int j = lane & 7, g = lane >> 3;
    const int aSel = g >> 1, bSel = g & 1;
    const uint32_t aRowB = (uint32_t)((wm * 32 + (g & 1) * 8 + j) * 128);
    const uint32_t bRowB = (uint32_t)((wn * 32 + (g >> 1) * 8 + j) * 128);

    float acc[2][4][4];
#pragma unroll
    for (int a = 0; a < 2; a++)
#pragma unroll
        for (int b = 0; b < 4; b++)
#pragma unroll
            for (int r = 0; r < 4; r++) acc[a][b][r] = 0.0f;

    const int NIT = K >> 6;   // K / 64

    auto load_stage = [&](int st, int k0) {
        const uint32_t base = sbase + st * STAGEB + ldRow128;
#pragma unroll
        for (int q = 0; q < 2; ++q) {
            const int c16 = ldcp + q;
            const uint32_t d = base + (uint32_t)((c16 ^ ldxor) * 16);
            cp16(d,      A + gA0 + k0 + q * 8);
            cp16(d + TB, B + gA0 + k0 + q * 8);   // same offsets: ld == K
        }
    };

    load_stage(0, 0);
    CP_COMMIT();
    if (NIT > 1) load_stage(1, 64);
    CP_COMMIT();

    for (int it = 0; it < NIT; ++it) {
        CP_WAIT(1);
        __syncthreads();
        const uint32_t sb = sbase + (it & 1) * STAGEB;
#pragma unroll
        for (int c = 0; c < 4; ++c) {          // four k16 blocks per stage
            const uint32_t bPhys = (uint32_t)((((2 * c) + bSel) ^ j) * 16);
            const uint32_t aPhys = (uint32_t)((((2 * c) + aSel) ^ j) * 16);
            uint32_t bh[8];
            ldsm4(bh,     sb + TB + bRowB + bPhys);
            ldsm4(bh + 4, sb + TB + bRowB + 16 * 128 + bPhys);
#pragma unroll
            for (int mi = 0; mi < 2; ++mi) {
                uint32_t ah[4];
                ldsm4(ah, sb + aRowB + mi * (16 * 128) + aPhys);
#pragma unroll
                for (int ni = 0; ni < 4; ++ni) mma16816(acc[mi][ni], ah, &bh[ni * 2]);
            }
        }
        __syncthreads();
        if (it + 2 < NIT) load_stage(it & 1, (it + 2) * 64);
        CP_COMMIT();
    }

    // epilogue
    const int qp = lane & 3, rr = lane >> 2;
#pragma unroll
    for (int mi = 0; mi < 2; ++mi) {
#pragma unroll
        for (int ni = 0; ni < 4; ++ni) {
            const int row = m0 + wm * 32 + mi * 16 + rr;
            const int col = f0 + wn * 32 + ni * 8 + qp * 2;
            float2 v0 = make_float2(acc[mi][ni][0], acc[mi][ni][1]);
            float2 v1 = make_float2(acc[mi][ni][2], acc[mi][ni][3]);
            if (EPI == 0) {
                float2 b = *(const float2*)(bias + col);
                __half2 h0 = __floats2half2_rn(tanhf(v0.x + b.x), tanhf(v0.y + b.y));
                __half2 h1 = __floats2half2_rn(tanhf(v1.x + b.x), tanhf(v1.y + b.y));
                *(__half2*)(Ch + (size_t)row * ldc + col)       = h0;
                *(__half2*)(Ch + (size_t)(row + 8) * ldc + col) = h1;
            } else {
                if (EPI == 1) {
                    v0.x *= scale; v0.y *= scale; v1.x *= scale; v1.y *= scale;
                }
                *(float2*)(C + (size_t)row * ldc + col)       = v0;
                *(float2*)(C + (size_t)(row + 8) * ldc + col) = v1;
            }
        }
    }
}

// ===========================================================================
// x (N,D,L) -> flat (M,D) fp16 rounded once (transpose)
// ===========================================================================
__global__ __launch_bounds__(256) void xhalf(const float* __restrict__ x,
                                             fp16* __restrict__ oh)
{
    __shared__ float t[32][33];
    const int z = blockIdx.z;
    const float* in = x + (size_t)z * DIM * LSEQ;
    const int l0 = blockIdx.x * 32, d0 = blockIdx.y * 32;
    const int xx = threadIdx.x & 31, yy = threadIdx.x >> 5;
#pragma unroll
    for (int i = 0; i < 32; i += 8)
        t[yy + i][xx] = in[(size_t)(d0 + yy + i) * LSEQ + l0 + xx];
    __syncthreads();
#pragma unroll
    for (int i = 0; i < 32; i += 8) {
        size_t o = (size_t)(z * LSEQ + l0 + yy + i) * DIM + d0 + xx;
        oh[o] = __float2half_rn(t[xx][yy + i]);
    }
}

// weights: round once to fp16; grid.y selects q/k/v
__global__ __launch_bounds__(256) void wsplit(const float* __restrict__ wq,
                                              const float* __restrict__ wk,
                                              const float* __restrict__ wv,
                                              fp16* __restrict__ h)
{
    const int n = FD * DIM;
    const float* w = (blockIdx.y == 0) ? wq : (blockIdx.y == 1) ? wk : wv;
    int i = blockIdx.x * 256 + threadIdx.x;
    if (i < n) h[blockIdx.y * n + i] = __float2half_rn(w[i]);
}

// ===========================================================================
// double instance norm: fp16 raw row -> fp16 row (grid.y = q/k/v)
// ===========================================================================
__device__ __forceinline__ float rsum128(float x, volatile float* red, int tid)
{
#pragma unroll
    for (int o = 16; o > 0; o >>= 1) x += __shfl_down_sync(0xffffffffu, x, o);
    if ((tid & 31) == 0) red[tid >> 5] = x;
    __syncthreads();
    float t = (red[0] + red[1]) + (red[2] + red[3]);
    __syncthreads();
    return t;
}

__global__ __launch_bounds__(128) void inorm_half(const fp16* __restrict__ raw,
                                                  fp16* __restrict__ qh,
                                                  fp16* __restrict__ kh,
                                                  fp16* __restrict__ vh)
{
    const int which = blockIdx.y;
    raw += (size_t)which * MF;
    fp16* oh = (which == 0) ? qh : (which == 1) ? kh : vh;

    const __half2* row = (const __half2*)(raw + (size_t)blockIdx.x * FD);
    __shared__ float red[4];
    const int tid = threadIdx.x;
    float2 a = __half22float2(row[tid * 2]);
    float2 b = __half22float2(row[tid * 2 + 1]);
    float4 v = make_float4(a.x, a.y, b.x, b.y);

    float s  = rsum128(v.x + v.y + v.z + v.w, red, tid);
    float mu = s * (1.0f / FD);
    v.x -= mu; v.y -= mu; v.z -= mu; v.w -= mu;
    float sq = rsum128(v.x * v.x + v.y * v.y + v.z * v.z + v.w * v.w, red, tid);
    float r1 = rsqrtf(sq * (1.0f / FD) + EPSN);
    v.x *= r1; v.y *= r1; v.z *= r1; v.w *= r1;

    float s2  = rsum128(v.x + v.y + v.z + v.w, red, tid);
    float mu2 = s2 * (1.0f / FD);
    v.x -= mu2; v.y -= mu2; v.z -= mu2; v.w -= mu2;
    float sq2 = rsum128(v.x * v.x + v.y * v.y + v.z * v.z + v.w * v.w, red, tid);
    float r2  = rsqrtf(sq2 * (1.0f / FD) + EPSN);
    v.x *= r2; v.y *= r2; v.z *= r2; v.w *= r2;

    __half2* o2 = (__half2*)(oh + (size_t)blockIdx.x * FD + tid * 4);
    o2[0] = __floats2half2_rn(v.x, v.y);
    o2[1] = __floats2half2_rn(v.z, v.w);
}

// ===========================================================================
// softmax: fp32 scores row -> fp16 prob row
// ===========================================================================
__global__ __launch_bounds__(256) void softmax_half(const float* __restrict__ S,
                                                    fp16* __restrict__ ph)
{
    const float* row = S + (size_t)blockIdx.x * LSEQ;
    __shared__ float red[8];
    const int tid = threadIdx.x;

    float v[9];
    float mx = -1e30f;
#pragma unroll
    for (int i = 0; i < 9; i++) { v[i] = row[tid + i * 256]; mx = fmaxf(mx, v[i]); }
#pragma unroll
    for (int o = 16; o > 0; o >>= 1) mx = fmaxf(mx, __shfl_xor_sync(0xffffffffu, mx, o));
    if ((tid & 31) == 0) red[tid >> 5] = mx;
    __syncthreads();
    mx = red[0];
#pragma unroll
    for (int w = 1; w < 8; w++) mx = fmaxf(mx, red[w]);
    __syncthreads();

    float s = 0.0f;
#pragma unroll
    for (int i = 0; i < 9; i++) { v[i] = expf(v[i] - mx); s += v[i]; }
#pragma unroll
    for (int o = 16; o > 0; o >>= 1) s += __shfl_xor_sync(0xffffffffu, s, o);
    if ((tid & 31) == 0) red[tid >> 5] = s;
    __syncthreads();
    s = ((red[0] + red[1]) + (red[2] + red[3])) + ((red[4] + red[5]) + (red[6] + red[7]));
    float inv = 1.0f / s;

    size_t o0 = (size_t)blockIdx.x * LSEQ + tid;
#pragma unroll
    for (int i = 0; i < 9; i++)
        ph[o0 + i * 256] = __float2half_rn(v[i] * inv);
}

// ===========================================================================
// V (L,F) -> VT (F,L) per batch
// ===========================================================================
__global__ __launch_bounds__(256) void vtrans(const fp16* __restrict__ ih,
                                              fp16* __restrict__ oh)
{
    __shared__ fp16 t[32][34];
    const int z = blockIdx.z;
    const size_t base = (size_t)z * LSEQ * FD;
    const int f0 = blockIdx.x * 32, l0 = blockIdx.y * 32;
    const int xx = threadIdx.x & 31, yy = threadIdx.x >> 5;

#pragma unroll
    for (int i = 0; i < 32; i += 8)
        t[yy + i][xx] = ih[base + (size_t)(l0 + yy + i) * FD + f0 + xx];
    __syncthreads();
#pragma unroll
    for (int i = 0; i < 32; i += 8)
        oh[base + (size_t)(f0 + yy + i) * LSEQ + l0 + xx] = t[xx][yy + i];
}

// ===========================================================================
extern "C" void kernel_launch(void* const* d_in, const int* in_sizes, int n_in,
                              void* d_out, int out_size)
{
    const float* x  = (const float*)d_in[0];
    const float* Wq = (const float*)d_in[1];
    const float* bq = (const float*)d_in[2];
    const float* Wk = (const float*)d_in[3];
    const float* bk = (const float*)d_in[4];
    const float* Wv = (const float*)d_in[5];
    const float* bv = (const float*)d_in[6];
    float* out = (float*)d_out;

    fp16 *pFh, *pWh, *pQh, *pKh, *pVh, *pVTh, *pPh;
    float* pS;
    cudaGetSymbolAddress((void**)&pFh,  g_flat_h);
    cudaGetSymbolAddress((void**)&pWh,  g_Wh);
    cudaGetSymbolAddress((void**)&pQh,  g_Qh);
    cudaGetSymbolAddress((void**)&pKh,  g_Kh);
    cudaGetSymbolAddress((void**)&pVh,  g_Vh);
    cudaGetSymbolAddress((void**)&pVTh, g_VTh);
    cudaGetSymbolAddress((void**)&pPh,  g_Ph);
    cudaGetSymbolAddress((void**)&pS,   g_S);

    cudaFuncSetAttribute((const void*)gemm1<0>, cudaFuncAttributeMaxDynamicSharedMemorySize, GEMM_SMEM);
    cudaFuncSetAttribute((const void*)gemm1<1>, cudaFuncAttributeMaxDynamicSharedMemorySize, GEMM_SMEM);
    cudaFuncSetAttribute((const void*)gemm1<2>, cudaFuncAttributeMaxDynamicSharedMemorySize, GEMM_SMEM);

    const int WN = FD * DIM;
    fp16* qraw = (fp16*)pS;      // fp16 raw QKV staged in front of g_S (56MB < 170MB)

    // 1) transpose+round x, round weights
    xhalf<<<dim3(LSEQ / 32, DIM / 32, NB), 256>>>(x, pFh);
    wsplit<<<dim3((WN + 255) / 256, 3), 256>>>(Wq, Wk, Wv, pWh);

    // 2) all three projections in one launch -> fp16 raw (tanh applied)
    gemm1<0><<<dim3(FD / 128, MTOT / 128, 3), 512, GEMM_SMEM>>>(
        pFh, pWh, nullptr, qraw, bq, bk, bv, DIM, FD,
        0, (long long)WN, (long long)MF, 0.f);

    // 3) double inorm -> fp16 Q/K/V
    inorm_half<<<dim3(MTOT, 3), 128>>>(qraw, pQh, pKh, pVh);

    // 4) V -> VT
    vtrans<<<dim3(FD / 32, LSEQ / 32, NB), 256>>>(pVh, pVTh);

    // 5) scores = (Q K^T) * scale  (fp32, overwrites raw staging)
    gemm1<1><<<dim3(LSEQ / 128, LSEQ / 128, NB), 512, GEMM_SMEM>>>(
        pQh, pKh, pS, nullptr, nullptr, nullptr, nullptr, FD, LSEQ,
        (long long)LSEQ * FD, (long long)LSEQ * FD, (long long)LSEQ * LSEQ, SCORE_SCALE);

    // 6) softmax -> fp16 P
    softmax_half<<<NB * LSEQ, 256>>>(pS, pPh);

    // 7) out = P @ V
    gemm1<2><<<dim3(FD / 128, LSEQ / 128, NB), 512, GEMM_SMEM>>>(
        pPh, pVTh, out, nullptr, nullptr, nullptr, nullptr, LSEQ, FD,
        (long long)LSEQ * LSEQ, (long long)FD * LSEQ, (long long)LSEQ * FD, 1.f);
}

// round 11
// speedup vs baseline: 1.9279x; 1.0303x over previous
#include <cuda_runtime.h>
#include <cuda_fp16.h>
#include <cstdint>

#define NB    8
#define DIM   512
#define LSEQ  2304
#define FD    512
#define MTOT  (NB * LSEQ)         // 18432
#define MF    ((size_t)MTOT * FD) // 9437184
#define EPSN  1e-5f
#define SCORE_SCALE 0.044194173824159216f   // 1/sqrt(512)

typedef __half fp16;

// ---------------- scratch (device globals) ----------------
__device__ fp16  g_flat_h[MF];                       // x^T rounded once
__device__ fp16  g_Wh[3][FD * DIM];                  // W rounded once
__device__ fp16  g_Qh[MF];
__device__ fp16  g_Kh[MF];
__device__ fp16  g_Vh[MF];
__device__ fp16  g_VTh[MF];                          // V^T per batch (F, L)
__device__ fp16  g_Ph[(size_t)NB * LSEQ * LSEQ];     // probs fp16
__device__ float g_S[(size_t)NB * LSEQ * LSEQ];      // scores fp32; front doubles as fp16 raw QKV

// ---------------- PTX helpers ----------------
__device__ __forceinline__ uint32_t smem_u32(const void* p) {
    uint32_t a;
    asm("{ .reg .u64 t; cvta.to.shared.u64 t, %1; cvt.u32.u64 %0, t; }" : "=r"(a) : "l"(p));
    return a;
}
__device__ __forceinline__ void cp16(uint32_t dst, const void* src) {
    asm volatile("cp.async.cg.shared.global [%0], [%1], 16;" :: "r"(dst), "l"(src));
}
#define CP_COMMIT() asm volatile("cp.async.commit_group;" ::: "memory")
#define CP_WAIT(N)  asm volatile("cp.async.wait_group %0;" :: "n"(N) : "memory")

__device__ __forceinline__ void ldsm4(uint32_t* r, uint32_t addr) {
    asm volatile("ldmatrix.sync.aligned.m8n8.x4.shared.b16 {%0,%1,%2,%3}, [%4];"
                 : "=r"(r[0]), "=r"(r[1]), "=r"(r[2]), "=r"(r[3]) : "r"(addr));
}
__device__ __forceinline__ void mma16816(float* c, const uint32_t* a, const uint32_t* b) {
    asm volatile("mma.sync.aligned.m16n8k16.row.col.f32.f16.f16.f32 "
                 "{%0,%1,%2,%3}, {%4,%5,%6,%7}, {%8,%9}, {%0,%1,%2,%3};"
                 : "+f"(c[0]), "+f"(c[1]), "+f"(c[2]), "+f"(c[3])
                 : "r"(a[0]), "r"(a[1]), "r"(a[2]), "r"(a[3]), "r"(b[0]), "r"(b[1]));
}

// ---------------- SMEM geometry ----------------
// tile: 128 rows x 64 fp16 = 128B/row, XOR-swizzled = 16384 B
#define TB 16384
#define STAGEB (2 * TB)           // A | B
#define GEMM_SMEM (2 * STAGEB)    // 64 KB

// ===========================================================================
// 1-term fp16 GEMM, fp32 accum, 512 threads, warp tile 32x32 (high WLP).
// C[m,n] = sum_k A[m,k]*B[n,k]; A,B K-major, ld == K.
// EPI 0: fp16 out = tanh(acc + bias[z]);  EPI 1: fp32 out = acc*scale;
// EPI 2: fp32 out = acc.
// ===========================================================================
template <int EPI>
__global__ void __launch_bounds__(512, 2) gemm1(
    const fp16* __restrict__ A, const fp16* __restrict__ B,
    float* __restrict__ C, fp16* __restrict__ Ch,
    const float* __restrict__ b0, const float* __restrict__ b1,
    const float* __restrict__ b2,
    int K, int ldc,
    long long sA, long long sB, long long sC, float scale)
{
    extern __shared__ char smem[];
    const uint32_t sbase = smem_u32(smem);
    const int tid  = threadIdx.x;
    const int lane = tid & 31, wid = tid >> 5;       // 16 warps
    const int wm = wid >> 2, wn = wid & 3;           // 4m x 4n, warp tile 32x32

    const int m0 = blockIdx.y * 128;
    const int f0 = blockIdx.x * 128;
    A += (long long)blockIdx.z * sA + (size_t)m0 * K;
    B += (long long)blockIdx.z * sB + (size_t)f0 * K;
    if (EPI == 0) Ch += (long long)blockIdx.z * sC;
    else          C  += (long long)blockIdx.z * sC;
    const float* bias = (EPI == 0)
        ? ((blockIdx.z == 0) ? b0 : (blockIdx.z == 1) ? b1 : b2) : nullptr;

    // cp.async mapping: thread t -> row = t>>2, chunk pair = (t&3)*2 + q
    const int ldrow  = tid >> 2;
    const int ldcp   = (tid & 3) * 2;
    const int ldxor  = ldrow & 7;
    const size_t gA0 = (size_t)ldrow * K + ldcp * 8;
    const uint32_t ldRow128 = (uint32_t)(ldrow * 128);

    // ldmatrix lane mapping
    const int j = lane & 7, g = lane >> 3;
    const int aSel = g >> 1, bSel = g & 1;
    const uint32_t aRowB = (uint32_t)((wm * 32 + (g & 1) * 8 + j) * 128);
    const uint32_t bRowB = (uint32_t)((wn * 32 + (g >> 1) * 8 + j) * 128);

    float acc[2][4][4];
#pragma unroll
    for (int a = 0; a < 2; a++)
#pragma unroll
        for (int b = 0; b < 4; b++)
#pragma unroll
            for (int r = 0; r < 4; r++) acc[a][b][r] = 0.0f;

    const int NIT = K >> 6;   // K / 64

    auto load_stage = [&](int st, int k0) {
        const uint32_t base = sbase + st * STAGEB + ldRow128;
#pragma unroll
        for (int q = 0; q < 2; ++q) {
            const int c16 = ldcp + q;
            const uint32_t d = base + (uint32_t)((c16 ^ ldxor) * 16);
            cp16(d,      A + gA0 + k0 + q * 8);
            cp16(d + TB, B + gA0 + k0 + q * 8);   // same offsets: ld == K
        }
    };

    load_stage(0, 0);
    CP_COMMIT();
    if (NIT > 1) load_stage(1, 64);
    CP_COMMIT();

    for (int it = 0; it < NIT; ++it) {
        CP_WAIT(1);
        __syncthreads();
        const uint32_t sb = sbase + (it & 1) * STAGEB;
#pragma unroll
        for (int c = 0; c < 4; ++c) {          // four k16 blocks per stage
            const uint32_t bPhys = (uint32_t)((((2 * c) + bSel) ^ j) * 16);
            const uint32_t aPhys = (uint32_t)((((2 * c) + aSel) ^ j) * 16);
            uint32_t bh[8];
            ldsm4(bh,     sb + TB + bRowB + bPhys);
            ldsm4(bh + 4, sb + TB + bRowB + 16 * 128 + bPhys);
#pragma unroll
            for (int mi = 0; mi < 2; ++mi) {
                uint32_t ah[4];
                ldsm4(ah, sb + aRowB + mi * (16 * 128) + aPhys);
#pragma unroll
                for (int ni = 0; ni < 4; ++ni) mma16816(acc[mi][ni], ah, &bh[ni * 2]);
            }
        }
        __syncthreads();
        if (it + 2 < NIT) load_stage(it & 1, (it + 2) * 64);
        CP_COMMIT();
    }

    // epilogue
    const int qp = lane & 3, rr = lane >> 2;
#pragma unroll
    for (int mi = 0; mi < 2; ++mi) {
#pragma unroll
        for (int ni = 0; ni < 4; ++ni) {
            const int row = m0 + wm * 32 + mi * 16 + rr;
            const int col = f0 + wn * 32 + ni * 8 + qp * 2;
            float2 v0 = make_float2(acc[mi][ni][0], acc[mi][ni][1]);
            float2 v1 = make_float2(acc[mi][ni][2], acc[mi][ni][3]);
            if (EPI == 0) {
                float2 b = *(const float2*)(bias + col);
                __half2 h0 = __floats2half2_rn(tanhf(v0.x + b.x), tanhf(v0.y + b.y));
                __half2 h1 = __floats2half2_rn(tanhf(v1.x + b.x), tanhf(v1.y + b.y));
                *(__half2*)(Ch + (size_t)row * ldc + col)       = h0;
                *(__half2*)(Ch + (size_t)(row + 8) * ldc + col) = h1;
            } else {
                if (EPI == 1) {
                    v0.x *= scale; v0.y *= scale; v1.x *= scale; v1.y *= scale;
                }
                *(float2*)(C + (size_t)row * ldc + col)       = v0;
                *(float2*)(C + (size_t)(row + 8) * ldc + col) = v1;
            }
        }
    }
}

// ===========================================================================
// x (N,D,L) -> flat (M,D) fp16 rounded once (transpose)
// ===========================================================================
__global__ __launch_bounds__(256) void xhalf(const float* __restrict__ x,
                                             fp16* __restrict__ oh)
{
    __shared__ float t[32][33];
    const int z = blockIdx.z;
    const float* in = x + (size_t)z * DIM * LSEQ;
    const int l0 = blockIdx.x * 32, d0 = blockIdx.y * 32;
    const int xx = threadIdx.x & 31, yy = threadIdx.x >> 5;
#pragma unroll
    for (int i = 0; i < 32; i += 8)
        t[yy + i][xx] = in[(size_t)(d0 + yy + i) * LSEQ + l0 + xx];
    __syncthreads();
#pragma unroll
    for (int i = 0; i < 32; i += 8) {
        size_t o = (size_t)(z * LSEQ + l0 + yy + i) * DIM + d0 + xx;
        oh[o] = __float2half_rn(t[xx][yy + i]);
    }
}

// weights: round once to fp16; grid.y selects q/k/v
__global__ __launch_bounds__(256) void wsplit(const float* __restrict__ wq,
                                              const float* __restrict__ wk,
                                              const float* __restrict__ wv,
                                              fp16* __restrict__ h)
{
    const int n = FD * DIM;
    const float* w = (blockIdx.y == 0) ? wq : (blockIdx.y == 1) ? wk : wv;
    int i = blockIdx.x * 256 + threadIdx.x;
    if (i < n) h[blockIdx.y * n + i] = __float2half_rn(w[i]);
}

// ===========================================================================
// ANALYTIC double instance norm, ONE reduction pass:
//   y = (x-mu)*r1, mean(y)=0 exactly, var(y)=var/(var+eps)
//   z = (x-mu) * r1 * r2,  r1=rsqrt(var+eps), r2=rsqrt(var/(var+eps)+eps)
// fp16 raw row -> fp16 row (grid.y = q/k/v)
// ===========================================================================
__global__ __launch_bounds__(128) void inorm_half(const fp16* __restrict__ raw,
                                                  fp16* __restrict__ qh,
                                                  fp16* __restrict__ kh,
                                                  fp16* __restrict__ vh)
{
    const int which = blockIdx.y;
    raw += (size_t)which * MF;
    fp16* oh = (which == 0) ? qh : (which == 1) ? kh : vh;

    const __half2* row = (const __half2*)(raw + (size_t)blockIdx.x * FD);
    __shared__ float2 red[4];
    const int tid = threadIdx.x;
    float2 a = __half22float2(row[tid * 2]);
    float2 b = __half22float2(row[tid * 2 + 1]);
    float4 v = make_float4(a.x, a.y, b.x, b.y);

    // joint (sum, sumsq) reduction — single tree, single smem round
    float s  = (v.x + v.y) + (v.z + v.w);
    float sq = (v.x * v.x + v.y * v.y) + (v.z * v.z + v.w * v.w);
#pragma unroll
    for (int o = 16; o > 0; o >>= 1) {
        s  += __shfl_down_sync(0xffffffffu, s,  o);
        sq += __shfl_down_sync(0xffffffffu, sq, o);
    }
    if ((tid & 31) == 0) red[tid >> 5] = make_float2(s, sq);
    __syncthreads();
    float2 r01 = red[0], r23 = red[2];
    float2 r1v = red[1], r3v = red[3];
    s  = (r01.x + r1v.x) + (r23.x + r3v.x);
    sq = (r01.y + r1v.y) + (r23.y + r3v.y);

    const float mu  = s * (1.0f / FD);
    float var = fmaxf(sq * (1.0f / FD) - mu * mu, 0.0f);
    const float r1  = rsqrtf(var + EPSN);
    const float v2  = var * r1 * r1;             // var/(var+eps) = var(y)
    const float r2  = rsqrtf(v2 + EPSN);
    const float sc  = r1 * r2;

    v.x = (v.x - mu) * sc; v.y = (v.y - mu) * sc;
    v.z = (v.z - mu) * sc; v.w = (v.w - mu) * sc;

    __half2* o2 = (__half2*)(oh + (size_t)blockIdx.x * FD + tid * 4);
    o2[0] = __floats2half2_rn(v.x, v.y);
    o2[1] = __floats2half2_rn(v.z, v.w);
}

// ===========================================================================
// softmax: fp32 scores row -> fp16 prob row
// ===========================================================================
__global__ __launch_bounds__(256) void softmax_half(const float* __restrict__ S,
                                                    fp16* __restrict__ ph)
{
    const float* row = S + (size_t)blockIdx.x * LSEQ;
    __shared__ float red[8];
    const int tid = threadIdx.x;

    float v[9];
    float mx = -1e30f;
#pragma unroll
    for (int i = 0; i < 9; i++) { v[i] = row[tid + i * 256]; mx = fmaxf(mx, v[i]); }
#pragma unroll
    for (int o = 16; o > 0; o >>= 1) mx = fmaxf(mx, __shfl_xor_sync(0xffffffffu, mx, o));
    if ((tid & 31) == 0) red[tid >> 5] = mx;
    __syncthreads();
    mx = red[0];
#pragma unroll
    for (int w = 1; w < 8; w++) mx = fmaxf(mx, red[w]);
    __syncthreads();

    float s = 0.0f;
#pragma unroll
    for (int i = 0; i < 9; i++) { v[i] = expf(v[i] - mx); s += v[i]; }
#pragma unroll
    for (int o = 16; o > 0; o >>= 1) s += __shfl_xor_sync(0xffffffffu, s, o);
    if ((tid & 31) == 0) red[tid >> 5] = s;
    __syncthreads();
    s = ((red[0] + red[1]) + (red[2] + red[3])) + ((red[4] + red[5]) + (red[6] + red[7]));
    float inv = 1.0f / s;

    size_t o0 = (size_t)blockIdx.x * LSEQ + tid;
#pragma unroll
    for (int i = 0; i < 9; i++)
        ph[o0 + i * 256] = __float2half_rn(v[i] * inv);
}

// ===========================================================================
// V (L,F) -> VT (F,L) per batch
// ===========================================================================
__global__ __launch_bounds__(256) void vtrans(const fp16* __restrict__ ih,
                                              fp16* __restrict__ oh)
{
    __shared__ fp16 t[32][34];
    const int z = blockIdx.z;
    const size_t base = (size_t)z * LSEQ * FD;
    const int f0 = blockIdx.x * 32, l0 = blockIdx.y * 32;
    const int xx = threadIdx.x & 31, yy = threadIdx.x >> 5;

#pragma unroll
    for (int i = 0; i < 32; i += 8)
        t[yy + i][xx] = ih[base + (size_t)(l0 + yy + i) * FD + f0 + xx];
    __syncthreads();
#pragma unroll
    for (int i = 0; i < 32; i += 8)
        oh[base + (size_t)(f0 + yy + i) * LSEQ + l0 + xx] = t[xx][yy + i];
}

// ===========================================================================
extern "C" void kernel_launch(void* const* d_in, const int* in_sizes, int n_in,
                              void* d_out, int out_size)
{
    const float* x  = (const float*)d_in[0];
    const float* Wq = (const float*)d_in[1];
    const float* bq = (const float*)d_in[2];
    const float* Wk = (const float*)d_in[3];
    const float* bk = (const float*)d_in[4];
    const float* Wv = (const float*)d_in[5];
    const float* bv = (const float*)d_in[6];
    float* out = (float*)d_out;

    fp16 *pFh, *pWh, *pQh, *pKh, *pVh, *pVTh, *pPh;
    float* pS;
    cudaGetSymbolAddress((void**)&pFh,  g_flat_h);
    cudaGetSymbolAddress((void**)&pWh,  g_Wh);
    cudaGetSymbolAddress((void**)&pQh,  g_Qh);
    cudaGetSymbolAddress((void**)&pKh,  g_Kh);
    cudaGetSymbolAddress((void**)&pVh,  g_Vh);
    cudaGetSymbolAddress((void**)&pVTh, g_VTh);
    cudaGetSymbolAddress((void**)&pPh,  g_Ph);
    cudaGetSymbolAddress((void**)&pS,   g_S);

    cudaFuncSetAttribute((const void*)gemm1<0>, cudaFuncAttributeMaxDynamicSharedMemorySize, GEMM_SMEM);
    cudaFuncSetAttribute((const void*)gemm1<1>, cudaFuncAttributeMaxDynamicSharedMemorySize, GEMM_SMEM);
    cudaFuncSetAttribute((const void*)gemm1<2>, cudaFuncAttributeMaxDynamicSharedMemorySize, GEMM_SMEM);

    const int WN = FD * DIM;
    fp16* qraw = (fp16*)pS;      // fp16 raw QKV staged in front of g_S (56MB < 170MB)

    // 1) transpose+round x, round weights
    xhalf<<<dim3(LSEQ / 32, DIM / 32, NB), 256>>>(x, pFh);
    wsplit<<<dim3((WN + 255) / 256, 3), 256>>>(Wq, Wk, Wv, pWh);

    // 2) all three projections in one launch -> fp16 raw (tanh applied)
    gemm1<0><<<dim3(FD / 128, MTOT / 128, 3), 512, GEMM_SMEM>>>(
        pFh, pWh, nullptr, qraw, bq, bk, bv, DIM, FD,
        0, (long long)WN, (long long)MF, 0.f);

    // 3) analytic double inorm -> fp16 Q/K/V
    inorm_half<<<dim3(MTOT, 3), 128>>>(qraw, pQh, pKh, pVh);

    // 4) V -> VT
    vtrans<<<dim3(FD / 32, LSEQ / 32, NB), 256>>>(pVh, pVTh);

    // 5) scores = (Q K^T) * scale  (fp32, overwrites raw staging)
    gemm1<1><<<dim3(LSEQ / 128, LSEQ / 128, NB), 512, GEMM_SMEM>>>(
        pQh, pKh, pS, nullptr, nullptr, nullptr, nullptr, FD, LSEQ,
        (long long)LSEQ * FD, (long long)LSEQ * FD, (long long)LSEQ * LSEQ, SCORE_SCALE);

    // 6) softmax -> fp16 P
    softmax_half<<<NB * LSEQ, 256>>>(pS, pPh);

    // 7) out = P @ V
    gemm1<2><<<dim3(FD / 128, LSEQ / 128, NB), 512, GEMM_SMEM>>>(
        pPh, pVTh, out, nullptr, nullptr, nullptr, nullptr, LSEQ, FD,
        (long long)LSEQ * LSEQ, (long long)FD * LSEQ, (long long)LSEQ * FD, 1.f);
}

// round 12
// speedup vs baseline: 2.0124x; 1.0439x over previous
#include <cuda_runtime.h>
#include <cuda_fp16.h>
#include <cstdint>

#define NB    8
#define DIM   512
#define LSEQ  2304
#define FD    512
#define MTOT  (NB * LSEQ)         // 18432
#define MF    ((size_t)MTOT * FD) // 9437184
#define EPSN  1e-5f
#define SCORE_SCALE 0.044194173824159216f   // 1/sqrt(512)

typedef __half fp16;

// ---------------- scratch (device globals) ----------------
__device__ fp16  g_flat_h[MF];                       // x^T rounded once
__device__ fp16  g_Wh[3][FD * DIM];                  // W rounded once
__device__ fp16  g_Qh[MF];
__device__ fp16  g_Kh[MF];
__device__ fp16  g_Vh[MF];
__device__ fp16  g_Ph[(size_t)NB * LSEQ * LSEQ];     // probs fp16
__device__ float g_S[(size_t)NB * LSEQ * LSEQ];      // scores fp32; front doubles as fp16 raw QKV

// ---------------- PTX helpers ----------------
__device__ __forceinline__ uint32_t smem_u32(const void* p) {
    uint32_t a;
    asm("{ .reg .u64 t; cvta.to.shared.u64 t, %1; cvt.u32.u64 %0, t; }" : "=r"(a) : "l"(p));
    return a;
}
__device__ __forceinline__ void cp16(uint32_t dst, const void* src) {
    asm volatile("cp.async.cg.shared.global [%0], [%1], 16;" :: "r"(dst), "l"(src));
}
#define CP_COMMIT() asm volatile("cp.async.commit_group;" ::: "memory")
#define CP_WAIT(N)  asm volatile("cp.async.wait_group %0;" :: "n"(N) : "memory")

__device__ __forceinline__ void ldsm4(uint32_t* r, uint32_t addr) {
    asm volatile("ldmatrix.sync.aligned.m8n8.x4.shared.b16 {%0,%1,%2,%3}, [%4];"
                 : "=r"(r[0]), "=r"(r[1]), "=r"(r[2]), "=r"(r[3]) : "r"(addr));
}
__device__ __forceinline__ void ldsm4t(uint32_t* r, uint32_t addr) {
    asm volatile("ldmatrix.sync.aligned.m8n8.x4.trans.shared.b16 {%0,%1,%2,%3}, [%4];"
                 : "=r"(r[0]), "=r"(r[1]), "=r"(r[2]), "=r"(r[3]) : "r"(addr));
}
__device__ __forceinline__ void mma16816(float* c, const uint32_t* a, const uint32_t* b) {
    asm volatile("mma.sync.aligned.m16n8k16.row.col.f32.f16.f16.f32 "
                 "{%0,%1,%2,%3}, {%4,%5,%6,%7}, {%8,%9}, {%0,%1,%2,%3};"
                 : "+f"(c[0]), "+f"(c[1]), "+f"(c[2]), "+f"(c[3])
                 : "r"(a[0]), "r"(a[1]), "r"(a[2]), "r"(a[3]), "r"(b[0]), "r"(b[1]));
}

// ---------------- SMEM geometry ----------------
// A tile: 128 rows x 64 fp16 = 128B/row, XOR-swizzled = 16384 B
// B tile (TRB=1): 64 rows x 128 fp16 = 256B/row, chunk-XOR swizzled = 16384 B
#define TB 16384
#define STAGEB (2 * TB)           // A | B
#define GEMM_SMEM (2 * STAGEB)    // 64 KB

// ===========================================================================
// 1-term fp16 GEMM, fp32 accum, 512 threads, warp tile 32x32.
// C[m,n] = sum_k A[m,k]*B'[n,k]
//   TRB=0: B stored (n,k) K-major with ld == K (same as A geometry)
//   TRB=1: B stored (k,n) row-major with row stride ldb  -> ldmatrix.trans
// EPI 0: fp16 out = tanh(acc + bias[z]); EPI 1: fp32 out = acc*scale; EPI 2: fp32 out
// ===========================================================================
template <int EPI, int TRB>
__global__ void __launch_bounds__(512, 2) gemmN(
    const fp16* __restrict__ A, const fp16* __restrict__ B,
    float* __restrict__ C, fp16* __restrict__ Ch,
    const float* __restrict__ b0, const float* __restrict__ b1,
    const float* __restrict__ b2,
    int K, int ldb, int ldc,
    long long sA, long long sB, long long sC, float scale)
{
    extern __shared__ char smem[];
    const uint32_t sbase = smem_u32(smem);
    const int tid  = threadIdx.x;
    const int lane = tid & 31, wid = tid >> 5;       // 16 warps
    const int wm = wid >> 2, wn = wid & 3;           // 4m x 4n, warp tile 32x32

    const int m0 = blockIdx.y * 128;
    const int f0 = blockIdx.x * 128;
    A += (long long)blockIdx.z * sA + (size_t)m0 * K;
    if (TRB == 0) B += (long long)blockIdx.z * sB + (size_t)f0 * K;
    else          B += (long long)blockIdx.z * sB + f0;
    if (EPI == 0) Ch += (long long)blockIdx.z * sC;
    else          C  += (long long)blockIdx.z * sC;
    const float* bias = (EPI == 0)
        ? ((blockIdx.z == 0) ? b0 : (blockIdx.z == 1) ? b1 : b2) : nullptr;

    // A cp.async mapping: thread t -> row = t>>2, chunk pair = (t&3)*2 + q
    const int arow  = tid >> 2;
    const int acp   = (tid & 3) * 2;
    const int axor  = arow & 7;
    const size_t gA0 = (size_t)arow * K + acp * 8;
    const uint32_t aRow128 = (uint32_t)(arow * 128);

    // B cp.async mapping (TRB=1): thread t -> row = t>>3 (64 rows x 256B),
    // chunk pair = (t&7)*2 + q
    const int brow  = tid >> 3;
    const int bcp   = (tid & 7) * 2;
    const int bxor  = brow & 7;
    const uint32_t bRow256 = (uint32_t)(brow * 256);

    // ldmatrix lane mapping
    const int j = lane & 7, g = lane >> 3;
    const int aSel = g >> 1, bSel = g & 1;
    const uint32_t aRowB = (uint32_t)((wm * 32 + (g & 1) * 8 + j) * 128);
    const uint32_t bRowB = (uint32_t)((wn * 32 + (g >> 1) * 8 + j) * 128);  // TRB=0
    // TRB=1 trans mapping: block b = lane>>3, row r = lane&7
    const uint32_t tRowB = (uint32_t)((((g & 1) * 8) + j) * 256);   // (b&1)*8 + r
    const int tChunk0 = wn * 4 + (g >> 1);                          // + 2*t later, ^ r

    float acc[2][4][4];
#pragma unroll
    for (int a = 0; a < 2; a++)
#pragma unroll
        for (int b = 0; b < 4; b++)
#pragma unroll
            for (int r = 0; r < 4; r++) acc[a][b][r] = 0.0f;

    const int NIT = K >> 6;   // K / 64

    auto load_stage = [&](int st, int k0) {
        const uint32_t abase = sbase + st * STAGEB + aRow128;
#pragma unroll
        for (int q = 0; q < 2; ++q) {
            const uint32_t d = abase + (uint32_t)(((acp + q) ^ axor) * 16);
            cp16(d, A + gA0 + k0 + q * 8);
            if (TRB == 0)
                cp16(d + TB, B + gA0 + k0 + q * 8);   // same geometry, ld == K
        }
        if (TRB == 1) {
            const uint32_t bbase = sbase + st * STAGEB + TB + bRow256;
            const fp16* src = B + (size_t)(k0 + brow) * ldb + bcp * 8;
#pragma unroll
            for (int q = 0; q < 2; ++q)
                cp16(bbase + (uint32_t)(((bcp + q) ^ bxor) * 16), src + q * 8);
        }
    };

    load_stage(0, 0);
    CP_COMMIT();
    if (NIT > 1) load_stage(1, 64);
    CP_COMMIT();

    for (int it = 0; it < NIT; ++it) {
        CP_WAIT(1);
        __syncthreads();
        const uint32_t sb = sbase + (it & 1) * STAGEB;
#pragma unroll
        for (int c = 0; c < 4; ++c) {          // four k16 blocks per stage
            uint32_t bh[8];
            if (TRB == 0) {
                const uint32_t bPhys = (uint32_t)((((2 * c) + bSel) ^ j) * 16);
                ldsm4(bh,     sb + TB + bRowB + bPhys);
                ldsm4(bh + 4, sb + TB + bRowB + 16 * 128 + bPhys);
            } else {
                const uint32_t bb = sb + TB + c * 4096 + tRowB;
                ldsm4t(bh,     bb + (uint32_t)(((tChunk0)     ^ j) * 16));
                ldsm4t(bh + 4, bb + (uint32_t)(((tChunk0 + 2) ^ j) * 16));
            }
            const uint32_t aPhys = (uint32_t)((((2 * c) + aSel) ^ j) * 16);
#pragma unroll
            for (int mi = 0; mi < 2; ++mi) {
                uint32_t ah[4];
                ldsm4(ah, sb + aRowB + mi * (16 * 128) + aPhys);
#pragma unroll
                for (int ni = 0; ni < 4; ++ni) mma16816(acc[mi][ni], ah, &bh[ni * 2]);
            }
        }
        __syncthreads();
        if (it + 2 < NIT) load_stage(it & 1, (it + 2) * 64);
        CP_COMMIT();
    }

    // epilogue
    const int qp = lane & 3, rr = lane >> 2;
#pragma unroll
    for (int mi = 0; mi < 2; ++mi) {
#pragma unroll
        for (int ni = 0; ni < 4; ++ni) {
            const int row = m0 + wm * 32 + mi * 16 + rr;
            const int col = f0 + wn * 32 + ni * 8 + qp * 2;
            float2 v0 = make_float2(acc[mi][ni][0], acc[mi][ni][1]);
            float2 v1 = make_float2(acc[mi][ni][2], acc[mi][ni][3]);
            if (EPI == 0) {
                float2 b = *(const float2*)(bias + col);
                __half2 h0 = __floats2half2_rn(tanhf(v0.x + b.x), tanhf(v0.y + b.y));
                __half2 h1 = __floats2half2_rn(tanhf(v1.x + b.x), tanhf(v1.y + b.y));
                *(__half2*)(Ch + (size_t)row * ldc + col)       = h0;
                *(__half2*)(Ch + (size_t)(row + 8) * ldc + col) = h1;
            } else {
                if (EPI == 1) {
                    v0.x *= scale; v0.y *= scale; v1.x *= scale; v1.y *= scale;
                }
                *(float2*)(C + (size_t)row * ldc + col)       = v0;
                *(float2*)(C + (size_t)(row + 8) * ldc + col) = v1;
            }
        }
    }
}

// ===========================================================================
// x (N,D,L) -> flat (M,D) fp16 rounded once (transpose)
// ===========================================================================
__global__ __launch_bounds__(256) void xhalf(const float* __restrict__ x,
                                             fp16* __restrict__ oh)
{
    __shared__ float t[32][33];
    const int z = blockIdx.z;
    const float* in = x + (size_t)z * DIM * LSEQ;
    const int l0 = blockIdx.x * 32, d0 = blockIdx.y * 32;
    const int xx = threadIdx.x & 31, yy = threadIdx.x >> 5;
#pragma unroll
    for (int i = 0; i < 32; i += 8)
        t[yy + i][xx] = in[(size_t)(d0 + yy + i) * LSEQ + l0 + xx];
    __syncthreads();
#pragma unroll
    for (int i = 0; i < 32; i += 8) {
        size_t o = (size_t)(z * LSEQ + l0 + yy + i) * DIM + d0 + xx;
        oh[o] = __float2half_rn(t[xx][yy + i]);
    }
}

// weights: round once to fp16; grid.y selects q/k/v
__global__ __launch_bounds__(256) void wsplit(const float* __restrict__ wq,
                                              const float* __restrict__ wk,
                                              const float* __restrict__ wv,
                                              fp16* __restrict__ h)
{
    const int n = FD * DIM;
    const float* w = (blockIdx.y == 0) ? wq : (blockIdx.y == 1) ? wk : wv;
    int i = blockIdx.x * 256 + threadIdx.x;
    if (i < n) h[blockIdx.y * n + i] = __float2half_rn(w[i]);
}

// ===========================================================================
// Analytic double instance norm, warp-per-row (no block sync):
//   z = (x-mu) * r1 * r2,  r1=rsqrt(var+eps), r2=rsqrt(var*r1*r1+eps)
// 4 rows per 128-thread block; lane owns 16 halves (32B read/write).
// ===========================================================================
__global__ __launch_bounds__(128) void inorm_half(const fp16* __restrict__ raw,
                                                  fp16* __restrict__ qh,
                                                  fp16* __restrict__ kh,
                                                  fp16* __restrict__ vh)
{
    const int which = blockIdx.y;
    const int row   = blockIdx.x * 4 + (threadIdx.x >> 5);
    const int lane  = threadIdx.x & 31;
    raw += (size_t)which * MF;
    fp16* oh = (which == 0) ? qh : (which == 1) ? kh : vh;

    const uint4* src = (const uint4*)(raw + (size_t)row * FD);
    uint4 u0 = src[lane * 2];
    uint4 u1 = src[lane * 2 + 1];

    float2 f[8];
    f[0] = __half22float2(*(__half2*)&u0.x); f[1] = __half22float2(*(__half2*)&u0.y);
    f[2] = __half22float2(*(__half2*)&u0.z); f[3] = __half22float2(*(__half2*)&u0.w);
    f[4] = __half22float2(*(__half2*)&u1.x); f[5] = __half22float2(*(__half2*)&u1.y);
    f[6] = __half22float2(*(__half2*)&u1.z); f[7] = __half22float2(*(__half2*)&u1.w);

    float s = 0.0f, sq = 0.0f;
#pragma unroll
    for (int i = 0; i < 8; i++) {
        s  += f[i].x + f[i].y;
        sq += f[i].x * f[i].x + f[i].y * f[i].y;
    }
#pragma unroll
    for (int o = 16; o > 0; o >>= 1) {
        s  += __shfl_xor_sync(0xffffffffu, s,  o);
        sq += __shfl_xor_sync(0xffffffffu, sq, o);
    }

    const float mu  = s * (1.0f / FD);
    float var = fmaxf(sq * (1.0f / FD) - mu * mu, 0.0f);
    const float r1  = rsqrtf(var + EPSN);
    const float v2  = var * r1 * r1;             // var/(var+eps)
    const float r2  = rsqrtf(v2 + EPSN);
    const float sc  = r1 * r2;

    uint4 o0, o1;
    __half2* po = (__half2*)&o0;
#pragma unroll
    for (int i = 0; i < 4; i++)
        po[i] = __floats2half2_rn((f[i].x - mu) * sc, (f[i].y - mu) * sc);
    __half2* p1 = (__half2*)&o1;
#pragma unroll
    for (int i = 0; i < 4; i++)
        p1[i] = __floats2half2_rn((f[4 + i].x - mu) * sc, (f[4 + i].y - mu) * sc);

    uint4* dst = (uint4*)(oh + (size_t)row * FD);
    dst[lane * 2]     = o0;
    dst[lane * 2 + 1] = o1;
}

// ===========================================================================
// softmax: fp32 scores row -> fp16 prob row
// ===========================================================================
__global__ __launch_bounds__(256) void softmax_half(const float* __restrict__ S,
                                                    fp16* __restrict__ ph)
{
    const float* row = S + (size_t)blockIdx.x * LSEQ;
    __shared__ float red[8];
    const int tid = threadIdx.x;

    float v[9];
    float mx = -1e30f;
#pragma unroll
    for (int i = 0; i < 9; i++) { v[i] = row[tid + i * 256]; mx = fmaxf(mx, v[i]); }
#pragma unroll
    for (int o = 16; o > 0; o >>= 1) mx = fmaxf(mx, __shfl_xor_sync(0xffffffffu, mx, o));
    if ((tid & 31) == 0) red[tid >> 5] = mx;
    __syncthreads();
    mx = red[0];
#pragma unroll
    for (int w = 1; w < 8; w++) mx = fmaxf(mx, red[w]);
    __syncthreads();

    float s = 0.0f;
#pragma unroll
    for (int i = 0; i < 9; i++) { v[i] = expf(v[i] - mx); s += v[i]; }
#pragma unroll
    for (int o = 16; o > 0; o >>= 1) s += __shfl_xor_sync(0xffffffffu, s, o);
    if ((tid & 31) == 0) red[tid >> 5] = s;
    __syncthreads();
    s = ((red[0] + red[1]) + (red[2] + red[3])) + ((red[4] + red[5]) + (red[6] + red[7]));
    float inv = 1.0f / s;

    size_t o0 = (size_t)blockIdx.x * LSEQ + tid;
#pragma unroll
    for (int i = 0; i < 9; i++)
        ph[o0 + i * 256] = __float2half_rn(v[i] * inv);
}

// ===========================================================================
extern "C" void kernel_launch(void* const* d_in, const int* in_sizes, int n_in,
                              void* d_out, int out_size)
{
    const float* x  = (const float*)d_in[0];
    const float* Wq = (const float*)d_in[1];
    const float* bq = (const float*)d_in[2];
    const float* Wk = (const float*)d_in[3];
    const float* bk = (const float*)d_in[4];
    const float* Wv = (const float*)d_in[5];
    const float* bv = (const float*)d_in[6];
    float* out = (float*)d_out;

    fp16 *pFh, *pWh, *pQh, *pKh, *pVh, *pPh;
    float* pS;
    cudaGetSymbolAddress((void**)&pFh, g_flat_h);
    cudaGetSymbolAddress((void**)&pWh, g_Wh);
    cudaGetSymbolAddress((void**)&pQh, g_Qh);
    cudaGetSymbolAddress((void**)&pKh, g_Kh);
    cudaGetSymbolAddress((void**)&pVh, g_Vh);
    cudaGetSymbolAddress((void**)&pPh, g_Ph);
    cudaGetSymbolAddress((void**)&pS,  g_S);

    cudaFuncSetAttribute((const void*)gemmN<0, 0>, cudaFuncAttributeMaxDynamicSharedMemorySize, GEMM_SMEM);
    cudaFuncSetAttribute((const void*)gemmN<1, 0>, cudaFuncAttributeMaxDynamicSharedMemorySize, GEMM_SMEM);
    cudaFuncSetAttribute((const void*)gemmN<2, 1>, cudaFuncAttributeMaxDynamicSharedMemorySize, GEMM_SMEM);

    const int WN = FD * DIM;
    fp16* qraw = (fp16*)pS;      // fp16 raw QKV staged in front of g_S (56MB < 170MB)

    // 1) transpose+round x, round weights
    xhalf<<<dim3(LSEQ / 32, DIM / 32, NB), 256>>>(x, pFh);
    wsplit<<<dim3((WN + 255) / 256, 3), 256>>>(Wq, Wk, Wv, pWh);

    // 2) all three projections in one launch -> fp16 raw (tanh applied)
    gemmN<0, 0><<<dim3(FD / 128, MTOT / 128, 3), 512, GEMM_SMEM>>>(
        pFh, pWh, nullptr, qraw, bq, bk, bv, DIM, DIM, FD,
        0, (long long)WN, (long long)MF, 0.f);

    // 3) analytic double inorm (warp per row) -> fp16 Q/K/V
    inorm_half<<<dim3(MTOT / 4, 3), 128>>>(qraw, pQh, pKh, pVh);

    // 4) scores = (Q K^T) * scale  (fp32, overwrites raw staging)
    gemmN<1, 0><<<dim3(LSEQ / 128, LSEQ / 128, NB), 512, GEMM_SMEM>>>(
        pQh, pKh, pS, nullptr, nullptr, nullptr, nullptr, FD, FD, LSEQ,
        (long long)LSEQ * FD, (long long)LSEQ * FD, (long long)LSEQ * LSEQ, SCORE_SCALE);

    // 5) softmax -> fp16 P
    softmax_half<<<NB * LSEQ, 256>>>(pS, pPh);

    // 6) out = P @ V, B read directly from V (k,n) via ldmatrix.trans
    gemmN<2, 1><<<dim3(FD / 128, LSEQ / 128, NB), 512, GEMM_SMEM>>>(
        pPh, pVh, out, nullptr, nullptr, nullptr, nullptr, LSEQ, FD, FD,
        (long long)LSEQ * LSEQ, (long long)LSEQ * FD, (long long)LSEQ * FD, 1.f);
}